// round 1
// baseline (speedup 1.0000x reference)
#include <cuda_runtime.h>
#include <cuda_bf16.h>

typedef unsigned long long ull;

// Problem constants
constexpr int B_   = 4;
constexpr int M_   = 2048;
constexpr int N_   = 16384;
constexpr int D_   = 64;
constexpr int C_   = 64;
constexpr int DIN  = 128;   // C + D
constexpr int DOUT = 64;
constexpr int TM   = 128;   // feat_down tile (M dimension)

// Scratch for concat[x = feat_up | feat_interp] : (B, N, 128) fp32 = 33.5 MB
__device__ float g_xbuf[(size_t)B_ * N_ * DIN];

// ---------- packed f32x2 helpers ----------
__device__ __forceinline__ ull pk2(float lo, float hi) {
    ull r; asm("mov.b64 %0, {%1, %2};" : "=l"(r) : "f"(lo), "f"(hi)); return r;
}
__device__ __forceinline__ void upk2(ull v, float& lo, float& hi) {
    asm("mov.b64 {%0, %1}, %2;" : "=f"(lo), "=f"(hi) : "l"(v));
}
__device__ __forceinline__ ull ffma2(ull a, ull b, ull c) {
    ull d; asm("fma.rn.f32x2 %0, %1, %2, %3;" : "=l"(d) : "l"(a), "l"(b), "l"(c)); return d;
}

// ============================================================================
// Kernel A: inverse-distance interpolation + concat -> g_xbuf
// grid (N/128, B), block 128. One thread = one up-point.
// ============================================================================
__global__ __launch_bounds__(128) void interp_kernel(
    const float* __restrict__ xyz_down,   // (B, M, 3)
    const float* __restrict__ xyz_up,     // (B, N, 3)
    const float* __restrict__ feat_down,  // (B, M, 64)
    const float* __restrict__ feat_up)    // (B, N, 64)
{
    __shared__ float  sx[TM], sy[TM], sz[TM], sb2[TM];
    __shared__ float4 sf[TM * 16];        // TM x 64 floats

    const int tid = threadIdx.x;
    const int b   = blockIdx.y;
    const int n   = blockIdx.x * 128 + tid;

    const float* xu = xyz_up + (size_t)(b * N_ + n) * 3;
    const float px = xu[0], py = xu[1], pz = xu[2];
    const float a2 = px * px + py * py + pz * pz;

    ull acc[32];
#pragma unroll
    for (int i = 0; i < 32; i++) acc[i] = 0ull;   // {0.f, 0.f}
    float rsum = 0.f;

    const float*  xd_b = xyz_down + (size_t)b * M_ * 3;
    const float4* fd_b = (const float4*)(feat_down + (size_t)b * M_ * D_);

    for (int t = 0; t < M_ / TM; ++t) {
        __syncthreads();   // previous tile fully consumed
        // load xyz tile + |b|^2 (one point per thread)
        {
            const float* src = xd_b + t * TM * 3;
            float bx = src[tid * 3 + 0];
            float by = src[tid * 3 + 1];
            float bz = src[tid * 3 + 2];
            sx[tid] = bx; sy[tid] = by; sz[tid] = bz;
            sb2[tid] = bx * bx + by * by + bz * bz;
        }
        // load feat tile (128 x 64 floats = 2048 float4)
        {
            const float4* src = fd_b + t * TM * 16;
#pragma unroll
            for (int q = tid; q < TM * 16; q += 128) sf[q] = src[q];
        }
        __syncthreads();

#pragma unroll 2
        for (int m = 0; m < TM; ++m) {
            // match reference expansion: d = |a|^2 + |b|^2 - 2 a.b
            float dot = px * sx[m] + py * sy[m] + pz * sz[m];
            float d   = a2 + sb2[m] - 2.0f * dot;
            float r   = __fdividef(1.0f, d + 1e-8f);
            rsum += r;
            ull r2 = pk2(r, r);
            const float4* fm = &sf[m * 16];
#pragma unroll
            for (int k = 0; k < 16; k++) {
                float4 v = fm[k];
                acc[2 * k]     = ffma2(r2, pk2(v.x, v.y), acc[2 * k]);
                acc[2 * k + 1] = ffma2(r2, pk2(v.z, v.w), acc[2 * k + 1]);
            }
        }
    }

    const float inv = __fdividef(1.0f, rsum);
    float4*       xrow = (float4*)(g_xbuf + (size_t)(b * N_ + n) * DIN);
    const float4* fu   = (const float4*)(feat_up + (size_t)(b * N_ + n) * C_);
#pragma unroll
    for (int k = 0; k < 16; k++) xrow[k] = fu[k];          // channels [0,64)
#pragma unroll
    for (int k = 0; k < 16; k++) {                         // channels [64,128)
        float l0, h0, l1, h1;
        upk2(acc[2 * k], l0, h0);
        upk2(acc[2 * k + 1], l1, h1);
        xrow[16 + k] = make_float4(l0 * inv, h0 * inv, l1 * inv, h1 * inv);
    }
}

// ============================================================================
// Kernel B: x(BN,128) -> [W1 + BN1 + relu] -> [W2 + BN2] -> out(BN,64)
// grid BN/128, block 128. One thread = one row. Dynamic SMEM ~164 KB.
// ============================================================================
__global__ __launch_bounds__(128) void mlp_kernel(
    const float* __restrict__ W1,  const float* __restrict__ b1,
    const float* __restrict__ g1,  const float* __restrict__ be1,
    const float* __restrict__ mu1, const float* __restrict__ va1,
    const float* __restrict__ W2,  const float* __restrict__ b2,
    const float* __restrict__ g2,  const float* __restrict__ be2,
    const float* __restrict__ mu2, const float* __restrict__ va2,
    float* __restrict__ out)
{
    extern __shared__ float sm[];
    float*  sW1  = sm;                       // 16384 floats: W1[o][c] row-major
    float*  sW2t = sm + 16384;               // 8192 floats : W2^T [o][j]
    float4* xs   = (float4*)(sm + 24576);    // 128 rows x 33 float4 (pad)
    float*  sS1  = sm + 24576 + 16896;       // 128
    float*  sT1  = sS1 + 128;                // 128
    float*  sS2  = sT1 + 128;                // 64
    float*  sT2  = sS2 + 64;                 // 64

    const int    tid  = threadIdx.x;
    const size_t row0 = (size_t)blockIdx.x * 128;

    // stage W1
    {
        const float4* w4 = (const float4*)W1;
        float4*       d4 = (float4*)sW1;
        for (int i = tid; i < 4096; i += 128) d4[i] = w4[i];
    }
    // stage W2 transposed: sW2t[o*64 + j]
    for (int i = tid; i < 8192; i += 128) {
        int j = i >> 7, o = i & 127;
        sW2t[o * 64 + j] = W2[i];
    }
    // stage x tile (padded stride 33 float4)
    {
        const float4* g4 = (const float4*)(g_xbuf + row0 * DIN);
        for (int i = tid; i < 128 * 32; i += 128) {
            int r = i >> 5, q = i & 31;
            xs[r * 33 + q] = g4[i];
        }
    }
    // fold BN into scale/shift:  bn(x + bias) = x*s + ((bias-mu)*s + beta)
    {
        float s = g1[tid] * rsqrtf(va1[tid] + 1e-5f);
        sS1[tid] = s;
        sT1[tid] = (b1[tid] - mu1[tid]) * s + be1[tid];
    }
    if (tid < 64) {
        float s = g2[tid] * rsqrtf(va2[tid] + 1e-5f);
        sS2[tid] = s;
        sT2[tid] = (b2[tid] - mu2[tid]) * s + be2[tid];
    }
    __syncthreads();

    const float4* xr = xs + tid * 33;

    ull y[32];
#pragma unroll
    for (int i = 0; i < 32; i++) y[i] = 0ull;

    for (int ob = 0; ob < 16; ++ob) {           // hidden channels in blocks of 8
        ull h[8];
#pragma unroll
        for (int i = 0; i < 8; i++) h[i] = 0ull;
        const float4* w1b = (const float4*)(sW1 + ob * 8 * 128);
#pragma unroll 4
        for (int cb = 0; cb < 32; ++cb) {       // 4 input channels per step
            float4 xv = xr[cb];
            ull x01 = pk2(xv.x, xv.y), x23 = pk2(xv.z, xv.w);
#pragma unroll
            for (int oi = 0; oi < 8; ++oi) {
                float4 wv = w1b[oi * 32 + cb];
                h[oi] = ffma2(x01, pk2(wv.x, wv.y), h[oi]);
                h[oi] = ffma2(x23, pk2(wv.z, wv.w), h[oi]);
            }
        }
#pragma unroll
        for (int oi = 0; oi < 8; ++oi) {
            int o = ob * 8 + oi;
            float lo, hi; upk2(h[oi], lo, hi);
            float a = fmaxf(fmaf(lo + hi, sS1[o], sT1[o]), 0.0f);  // BN1 + relu
            ull ap = pk2(a, a);
            const float4* w2r = (const float4*)(sW2t + o * 64);
#pragma unroll
            for (int jj = 0; jj < 16; jj++) {
                float4 wv = w2r[jj];
                y[2 * jj]     = ffma2(ap, pk2(wv.x, wv.y), y[2 * jj]);
                y[2 * jj + 1] = ffma2(ap, pk2(wv.z, wv.w), y[2 * jj + 1]);
            }
        }
    }

    float4* orow = (float4*)(out + (row0 + tid) * DOUT);
#pragma unroll
    for (int jj = 0; jj < 16; jj++) {
        float l0, h0, l1, h1;
        upk2(y[2 * jj], l0, h0);
        upk2(y[2 * jj + 1], l1, h1);
        int j = 4 * jj;
        orow[jj] = make_float4(fmaf(l0, sS2[j + 0], sT2[j + 0]),
                               fmaf(h0, sS2[j + 1], sT2[j + 1]),
                               fmaf(l1, sS2[j + 2], sT2[j + 2]),
                               fmaf(h1, sS2[j + 3], sT2[j + 3]));
    }
}

// ============================================================================
extern "C" void kernel_launch(void* const* d_in, const int* in_sizes, int n_in,
                              void* d_out, int out_size)
{
    const float* xyz_down  = (const float*)d_in[0];
    const float* xyz_up    = (const float*)d_in[1];
    const float* feat_down = (const float*)d_in[2];
    const float* feat_up   = (const float*)d_in[3];
    const float* W1  = (const float*)d_in[4];
    const float* b1  = (const float*)d_in[5];
    const float* g1  = (const float*)d_in[6];
    const float* be1 = (const float*)d_in[7];
    const float* mu1 = (const float*)d_in[8];
    const float* va1 = (const float*)d_in[9];
    const float* W2  = (const float*)d_in[10];
    const float* b2  = (const float*)d_in[11];
    const float* g2  = (const float*)d_in[12];
    const float* be2 = (const float*)d_in[13];
    const float* mu2 = (const float*)d_in[14];
    const float* va2 = (const float*)d_in[15];
    float* out = (float*)d_out;

    dim3 gridA(N_ / 128, B_);
    interp_kernel<<<gridA, 128>>>(xyz_down, xyz_up, feat_down, feat_up);

    const int smemB = (24576 + 16896 + 384) * (int)sizeof(float);  // 167424 B
    cudaFuncSetAttribute(mlp_kernel,
                         cudaFuncAttributeMaxDynamicSharedMemorySize, smemB);
    mlp_kernel<<<(B_ * N_) / 128, 128, smemB>>>(
        W1, b1, g1, be1, mu1, va1, W2, b2, g2, be2, mu2, va2, out);
}

// round 3
// speedup vs baseline: 3.4127x; 3.4127x over previous
#include <cuda_runtime.h>
#include <cuda_bf16.h>

typedef unsigned int u32;

// Problem constants
constexpr int B_  = 4;
constexpr int M_  = 2048;
constexpr int N_  = 16384;
constexpr int DIN = 128;

// ---------------- device scratch ----------------
__device__ float g_xbuf[(size_t)B_ * N_ * DIN];               // concat x
__device__ __nv_bfloat16 g_fTh[(size_t)B_ * 64 * M_];         // featT hi (B,64,M)
__device__ __nv_bfloat16 g_fTl[(size_t)B_ * 64 * M_];         // featT lo
__device__ __nv_bfloat16 g_W1h[128 * 128], g_W1l[128 * 128];  // W1 rows o, cols c
__device__ __nv_bfloat16 g_W2h[64 * 128],  g_W2l[64 * 128];   // W2 rows j, cols o
__device__ float g_S1[128], g_T1[128], g_S2[64], g_T2[64];    // folded BN

// ---------------- helpers ----------------
__device__ __forceinline__ u32 smem_u32(const void* p) {
    u32 a;
    asm("{ .reg .u64 t; cvta.to.shared.u64 t, %1; cvt.u32.u64 %0, t; }" : "=r"(a) : "l"(p));
    return a;
}
// pack {lo, hi} floats into bf16x2 (lo -> bits[15:0])
__device__ __forceinline__ u32 cvt_bf2(float hi, float lo) {
    u32 r;
    asm("cvt.rn.bf16x2.f32 %0, %1, %2;" : "=r"(r) : "f"(hi), "f"(lo));
    return r;
}
__device__ __forceinline__ void ldsm_x2(u32& r0, u32& r1, u32 addr) {
    asm volatile("ldmatrix.sync.aligned.m8n8.x2.shared.b16 {%0, %1}, [%2];"
                 : "=r"(r0), "=r"(r1) : "r"(addr));
}
__device__ __forceinline__ void mma_bf16(float* c, const u32* a, u32 b0, u32 b1) {
    asm volatile(
        "mma.sync.aligned.m16n8k16.row.col.f32.bf16.bf16.f32 "
        "{%0,%1,%2,%3}, {%4,%5,%6,%7}, {%8,%9}, {%0,%1,%2,%3};"
        : "+f"(c[0]), "+f"(c[1]), "+f"(c[2]), "+f"(c[3])
        : "r"(a[0]), "r"(a[1]), "r"(a[2]), "r"(a[3]), "r"(b0), "r"(b1));
}
__device__ __forceinline__ void split_lo(u32 hpack, float f0, float f1, u32& lpack) {
    float e0 = __uint_as_float(hpack << 16);
    float e1 = __uint_as_float(hpack & 0xFFFF0000u);
    lpack = cvt_bf2(f1 - e1, f0 - e0);
}

// ============================================================================
// Prep 1: feat_down (B,M,64) f32 -> g_fTh/g_fTl (B,64,M) bf16 hi/lo
// ============================================================================
__global__ __launch_bounds__(256) void prep_feat(const float* __restrict__ feat_down) {
    __shared__ float sT[64][65];
    const int b = blockIdx.y, m0 = blockIdx.x * 64;
    const int tid = threadIdx.x;
#pragma unroll
    for (int j = 0; j < 4; ++j) {
        int i = tid + j * 256;
        int r = i >> 4, c4 = (i & 15) * 4;
        float4 v = *(const float4*)(feat_down + ((size_t)b * M_ + m0 + r) * 64 + c4);
        sT[c4 + 0][r] = v.x; sT[c4 + 1][r] = v.y;
        sT[c4 + 2][r] = v.z; sT[c4 + 3][r] = v.w;
    }
    __syncthreads();
#pragma unroll
    for (int j = 0; j < 8; ++j) {
        int u = tid + j * 256;
        int d = u >> 5, m2 = (u & 31) * 2;
        float f0 = sT[d][m2], f1 = sT[d][m2 + 1];
        u32 hp = cvt_bf2(f1, f0);
        u32 lp; split_lo(hp, f0, f1, lp);
        size_t o = (size_t)(b * 64 + d) * M_ + m0 + m2;
        *(u32*)(g_fTh + o) = hp;
        *(u32*)(g_fTl + o) = lp;
    }
}

// ============================================================================
// Prep 2: split W1/W2 to bf16 hi/lo; fold BN into scale/shift
// ============================================================================
__global__ __launch_bounds__(256) void prep_w(
    const float* __restrict__ W1, const float* __restrict__ b1,
    const float* __restrict__ g1, const float* __restrict__ be1,
    const float* __restrict__ mu1, const float* __restrict__ va1,
    const float* __restrict__ W2, const float* __restrict__ b2,
    const float* __restrict__ g2, const float* __restrict__ be2,
    const float* __restrict__ mu2, const float* __restrict__ va2)
{
    const int tid = threadIdx.x;
    for (int i = tid; i < 128 * 128; i += 256) {
        float w = W1[i];
        __nv_bfloat16 h = __float2bfloat16_rn(w);
        g_W1h[i] = h;
        g_W1l[i] = __float2bfloat16_rn(w - __bfloat162float(h));
    }
    for (int i = tid; i < 64 * 128; i += 256) {
        float w = W2[i];
        __nv_bfloat16 h = __float2bfloat16_rn(w);
        g_W2h[i] = h;
        g_W2l[i] = __float2bfloat16_rn(w - __bfloat162float(h));
    }
    if (tid < 128) {
        float s = g1[tid] * rsqrtf(va1[tid] + 1e-5f);
        g_S1[tid] = s;
        g_T1[tid] = (b1[tid] - mu1[tid]) * s + be1[tid];
    }
    if (tid < 64) {
        float s = g2[tid] * rsqrtf(va2[tid] + 1e-5f);
        g_S2[tid] = s;
        g_T2[tid] = (b2[tid] - mu2[tid]) * s + be2[tid];
    }
}

// ============================================================================
// Kernel A: interpolation via mma.sync. grid (N/128, B), 256 threads (8 warps).
// Each warp owns 16 rows x 64 channels of C. A (r weights) built in registers.
// ============================================================================
constexpr int BPITCH = 136;   // bf16 elems per smem B row (272 B)

__global__ __launch_bounds__(256, 2) void interp_kernel(
    const float* __restrict__ xyz_down,
    const float* __restrict__ xyz_up,
    const float* __restrict__ feat_up)
{
    __shared__ __align__(16) __nv_bfloat16 sBh[64 * BPITCH];
    __shared__ __align__(16) __nv_bfloat16 sBl[64 * BPITCH];
    __shared__ float4 sD[128];
    __shared__ float4 sUP[128];
    __shared__ float  sRS[128];

    const int tid = threadIdx.x, wid = tid >> 5, lane = tid & 31;
    const int b = blockIdx.y, n0 = blockIdx.x * 128;
    const int g = lane >> 2, tg = lane & 3;
    const int r0 = wid * 16;

    if (tid < 128) {
        const float* p = xyz_up + ((size_t)b * N_ + n0 + tid) * 3;
        float x = p[0], y = p[1], z = p[2];
        sUP[tid] = make_float4(x, y, z, x * x + y * y + z * z);
    }
    __syncthreads();

    const float4 uA = sUP[r0 + g];
    const float4 uB = sUP[r0 + 8 + g];

    float c[8][4];
#pragma unroll
    for (int i = 0; i < 8; ++i)
#pragma unroll
        for (int j = 0; j < 4; ++j) c[i][j] = 0.f;
    float rsA = 0.f, rsB = 0.f;

    const u32 baseBh = smem_u32(sBh);
    const u32 baseBl = smem_u32(sBl);
    const u32 lrow = (u32)(lane & 7) * (BPITCH * 2);          // bytes
    const u32 lkh  = (u32)((lane >> 3) & 1) * 16;             // +8 cols -> +16 B

    for (int t = 0; t < 16; ++t) {
        __syncthreads();
        // stage B tile (64 ch x 128 k), hi + lo
#pragma unroll
        for (int j = 0; j < 4; ++j) {
            int idx = tid + 256 * j;
            int d = idx >> 4, kc = (idx & 15) * 8;
            size_t go = (size_t)(b * 64 + d) * M_ + t * 128 + kc;
            *(uint4*)(sBh + d * BPITCH + kc) = *(const uint4*)(g_fTh + go);
            *(uint4*)(sBl + d * BPITCH + kc) = *(const uint4*)(g_fTl + go);
        }
        // stage down points (x,y,z,|b|^2+1e-8)
        if (tid < 128) {
            const float* p = xyz_down + ((size_t)b * M_ + t * 128 + tid) * 3;
            float x = p[0], y = p[1], z = p[2];
            sD[tid] = make_float4(x, y, z, x * x + y * y + z * z + 1e-8f);
        }
        __syncthreads();

#pragma unroll
        for (int ks = 0; ks < 8; ++ks) {
            const int kb = ks * 16 + tg * 2;
            float4 q0 = sD[kb], q1 = sD[kb + 1], q2 = sD[kb + 8], q3 = sD[kb + 9];

            float d00 = fmaf(fmaf(uA.z, q0.z, fmaf(uA.y, q0.y, uA.x * q0.x)), -2.f, uA.w + q0.w);
            float d01 = fmaf(fmaf(uA.z, q1.z, fmaf(uA.y, q1.y, uA.x * q1.x)), -2.f, uA.w + q1.w);
            float d02 = fmaf(fmaf(uA.z, q2.z, fmaf(uA.y, q2.y, uA.x * q2.x)), -2.f, uA.w + q2.w);
            float d03 = fmaf(fmaf(uA.z, q3.z, fmaf(uA.y, q3.y, uA.x * q3.x)), -2.f, uA.w + q3.w);
            float d10 = fmaf(fmaf(uB.z, q0.z, fmaf(uB.y, q0.y, uB.x * q0.x)), -2.f, uB.w + q0.w);
            float d11 = fmaf(fmaf(uB.z, q1.z, fmaf(uB.y, q1.y, uB.x * q1.x)), -2.f, uB.w + q1.w);
            float d12 = fmaf(fmaf(uB.z, q2.z, fmaf(uB.y, q2.y, uB.x * q2.x)), -2.f, uB.w + q2.w);
            float d13 = fmaf(fmaf(uB.z, q3.z, fmaf(uB.y, q3.y, uB.x * q3.x)), -2.f, uB.w + q3.w);

            float r00 = __fdividef(1.f, d00), r01 = __fdividef(1.f, d01);
            float r02 = __fdividef(1.f, d02), r03 = __fdividef(1.f, d03);
            float r10 = __fdividef(1.f, d10), r11 = __fdividef(1.f, d11);
            float r12 = __fdividef(1.f, d12), r13 = __fdividef(1.f, d13);

            rsA += (r00 + r01) + (r02 + r03);
            rsB += (r10 + r11) + (r12 + r13);

            u32 ah[4], al[4];
            ah[0] = cvt_bf2(r01, r00); split_lo(ah[0], r00, r01, al[0]);
            ah[1] = cvt_bf2(r11, r10); split_lo(ah[1], r10, r11, al[1]);
            ah[2] = cvt_bf2(r03, r02); split_lo(ah[2], r02, r03, al[2]);
            ah[3] = cvt_bf2(r13, r12); split_lo(ah[3], r12, r13, al[3]);

            const u32 koff = (u32)(ks * 32) + lkh;   // ks*16 cols -> 32 B
#pragma unroll
            for (int nt = 0; nt < 8; ++nt) {
                u32 off = (u32)(nt * 8 * BPITCH * 2) + lrow + koff;
                u32 bh0, bh1, bl0, bl1;
                ldsm_x2(bh0, bh1, baseBh + off);
                ldsm_x2(bl0, bl1, baseBl + off);
                mma_bf16(c[nt], ah, bh0, bh1);
                mma_bf16(c[nt], ah, bl0, bl1);
                mma_bf16(c[nt], al, bh0, bh1);
            }
        }
    }

    // rsum: reduce over the 4 lanes of each quad (they cover all k)
    rsA += __shfl_xor_sync(0xFFFFFFFFu, rsA, 1);
    rsA += __shfl_xor_sync(0xFFFFFFFFu, rsA, 2);
    rsB += __shfl_xor_sync(0xFFFFFFFFu, rsB, 1);
    rsB += __shfl_xor_sync(0xFFFFFFFFu, rsB, 2);
    if (tg == 0) { sRS[r0 + g] = rsA; sRS[r0 + 8 + g] = rsB; }
    __syncthreads();

    const float invA = __fdividef(1.f, sRS[r0 + g]);
    const float invB = __fdividef(1.f, sRS[r0 + 8 + g]);
    float* rowA = g_xbuf + ((size_t)(b * N_ + n0 + r0 + g)) * DIN + 64;
    float* rowB = g_xbuf + ((size_t)(b * N_ + n0 + r0 + 8 + g)) * DIN + 64;
#pragma unroll
    for (int nt = 0; nt < 8; ++nt) {
        *(float2*)(rowA + nt * 8 + 2 * tg) = make_float2(c[nt][0] * invA, c[nt][1] * invA);
        *(float2*)(rowB + nt * 8 + 2 * tg) = make_float2(c[nt][2] * invB, c[nt][3] * invB);
    }
    // feat_up -> channels [0,64)
#pragma unroll
    for (int j = 0; j < 8; ++j) {
        int i = tid + j * 256;
        int rr = i >> 4, q = i & 15;
        ((float4*)(g_xbuf + ((size_t)(b * N_ + n0 + rr)) * DIN))[q] =
            ((const float4*)(feat_up + ((size_t)(b * N_ + n0 + rr)) * 64))[q];
    }
}

// ============================================================================
// Kernel B: fused tensor MLP. grid BN/128, 256 threads (8 warps x 16 rows).
// GEMM1(128->128) + BN1 + relu -> repack -> GEMM2(128->64) + BN2.
// ============================================================================
constexpr int SMW1 = 128 * BPITCH;        // bf16 elems
constexpr int SMW2 = 64 * BPITCH;
constexpr int MLP_SMEM = (SMW1 * 2 + SMW2 * 2) * 2 + (128 + 128 + 64 + 64) * 4;

__global__ __launch_bounds__(256) void mlp_kernel(float* __restrict__ out) {
    extern __shared__ __align__(16) char sm[];
    __nv_bfloat16* sW1h = (__nv_bfloat16*)sm;
    __nv_bfloat16* sW1l = sW1h + SMW1;
    __nv_bfloat16* sW2h = sW1l + SMW1;
    __nv_bfloat16* sW2l = sW2h + SMW2;
    float* sS1 = (float*)(sW2l + SMW2);
    float* sT1 = sS1 + 128;
    float* sS2 = sT1 + 128;
    float* sT2 = sS2 + 64;

    const int tid = threadIdx.x, wid = tid >> 5, lane = tid & 31;
    const int g = lane >> 2, tg = lane & 3;
    const int r0 = wid * 16;

    // stage weights with pitch pad
    for (int i = tid; i < 2048; i += 256) {
        int r = i >> 4, q = (i & 15) * 8;
        *(uint4*)(sW1h + r * BPITCH + q) = ((const uint4*)g_W1h)[i];
        *(uint4*)(sW1l + r * BPITCH + q) = ((const uint4*)g_W1l)[i];
    }
    for (int i = tid; i < 1024; i += 256) {
        int r = i >> 4, q = (i & 15) * 8;
        *(uint4*)(sW2h + r * BPITCH + q) = ((const uint4*)g_W2h)[i];
        *(uint4*)(sW2l + r * BPITCH + q) = ((const uint4*)g_W2l)[i];
    }
    if (tid < 128) { sS1[tid] = g_S1[tid]; sT1[tid] = g_T1[tid]; }
    if (tid < 64)  { sS2[tid] = g_S2[tid]; sT2[tid] = g_T2[tid]; }
    __syncthreads();

    const size_t rowA = (size_t)blockIdx.x * 128 + r0 + g;
    const size_t rowB = rowA + 8;
    const float* xA = g_xbuf + rowA * DIN;
    const float* xB = g_xbuf + rowB * DIN;

    const u32 bW1h = smem_u32(sW1h), bW1l = smem_u32(sW1l);
    const u32 bW2h = smem_u32(sW2h), bW2l = smem_u32(sW2l);
    const u32 lrow = (u32)(lane & 7) * (BPITCH * 2);
    const u32 lkh  = (u32)((lane >> 3) & 1) * 16;

    // ---------------- GEMM1 ----------------
    float c1[16][4];
#pragma unroll
    for (int i = 0; i < 16; ++i)
#pragma unroll
        for (int j = 0; j < 4; ++j) c1[i][j] = 0.f;

#pragma unroll
    for (int ks = 0; ks < 8; ++ks) {
        float2 p0 = *(const float2*)(xA + ks * 16 + 2 * tg);
        float2 p1 = *(const float2*)(xA + ks * 16 + 2 * tg + 8);
        float2 p2 = *(const float2*)(xB + ks * 16 + 2 * tg);
        float2 p3 = *(const float2*)(xB + ks * 16 + 2 * tg + 8);
        u32 ah[4], al[4];
        ah[0] = cvt_bf2(p0.y, p0.x); split_lo(ah[0], p0.x, p0.y, al[0]);
        ah[1] = cvt_bf2(p2.y, p2.x); split_lo(ah[1], p2.x, p2.y, al[1]);
        ah[2] = cvt_bf2(p1.y, p1.x); split_lo(ah[2], p1.x, p1.y, al[2]);
        ah[3] = cvt_bf2(p3.y, p3.x); split_lo(ah[3], p3.x, p3.y, al[3]);

        const u32 koff = (u32)(ks * 32) + lkh;
#pragma unroll
        for (int nt = 0; nt < 16; ++nt) {
            u32 off = (u32)(nt * 8 * BPITCH * 2) + lrow + koff;
            u32 bh0, bh1, bl0, bl1;
            ldsm_x2(bh0, bh1, bW1h + off);
            ldsm_x2(bl0, bl1, bW1l + off);
            mma_bf16(c1[nt], ah, bh0, bh1);
            mma_bf16(c1[nt], ah, bl0, bl1);
            mma_bf16(c1[nt], al, bh0, bh1);
        }
    }

    // ---------------- BN1 + relu -> A2 fragments ----------------
    u32 a2h[8][4], a2l[8][4];
#pragma unroll
    for (int k2 = 0; k2 < 8; ++k2) {
        int nt0 = 2 * k2, nt1 = 2 * k2 + 1;
        int o0 = nt0 * 8 + 2 * tg, o1 = o0 + 1;
        int o2 = nt1 * 8 + 2 * tg, o3 = o2 + 1;
        float hA0 = fmaxf(fmaf(c1[nt0][0], sS1[o0], sT1[o0]), 0.f);
        float hA1 = fmaxf(fmaf(c1[nt0][1], sS1[o1], sT1[o1]), 0.f);
        float hB0 = fmaxf(fmaf(c1[nt0][2], sS1[o0], sT1[o0]), 0.f);
        float hB1 = fmaxf(fmaf(c1[nt0][3], sS1[o1], sT1[o1]), 0.f);
        float hA2 = fmaxf(fmaf(c1[nt1][0], sS1[o2], sT1[o2]), 0.f);
        float hA3 = fmaxf(fmaf(c1[nt1][1], sS1[o3], sT1[o3]), 0.f);
        float hB2 = fmaxf(fmaf(c1[nt1][2], sS1[o2], sT1[o2]), 0.f);
        float hB3 = fmaxf(fmaf(c1[nt1][3], sS1[o3], sT1[o3]), 0.f);
        a2h[k2][0] = cvt_bf2(hA1, hA0); split_lo(a2h[k2][0], hA0, hA1, a2l[k2][0]);
        a2h[k2][1] = cvt_bf2(hB1, hB0); split_lo(a2h[k2][1], hB0, hB1, a2l[k2][1]);
        a2h[k2][2] = cvt_bf2(hA3, hA2); split_lo(a2h[k2][2], hA2, hA3, a2l[k2][2]);
        a2h[k2][3] = cvt_bf2(hB3, hB2); split_lo(a2h[k2][3], hB2, hB3, a2l[k2][3]);
    }

    // ---------------- GEMM2 ----------------
    float c2[8][4];
#pragma unroll
    for (int i = 0; i < 8; ++i)
#pragma unroll
        for (int j = 0; j < 4; ++j) c2[i][j] = 0.f;

#pragma unroll
    for (int k2 = 0; k2 < 8; ++k2) {
        const u32 koff = (u32)(k2 * 32) + lkh;
#pragma unroll
        for (int nt = 0; nt < 8; ++nt) {
            u32 off = (u32)(nt * 8 * BPITCH * 2) + lrow + koff;
            u32 bh0, bh1, bl0, bl1;
            ldsm_x2(bh0, bh1, bW2h + off);
            ldsm_x2(bl0, bl1, bW2l + off);
            mma_bf16(c2[nt], a2h[k2], bh0, bh1);
            mma_bf16(c2[nt], a2h[k2], bl0, bl1);
            mma_bf16(c2[nt], a2l[k2], bh0, bh1);
        }
    }

    // ---------------- BN2 + store ----------------
    float* oA = out + rowA * 64;
    float* oB = out + rowB * 64;
#pragma unroll
    for (int nt = 0; nt < 8; ++nt) {
        int j0 = nt * 8 + 2 * tg, j1 = j0 + 1;
        *(float2*)(oA + j0) = make_float2(fmaf(c2[nt][0], sS2[j0], sT2[j0]),
                                          fmaf(c2[nt][1], sS2[j1], sT2[j1]));
        *(float2*)(oB + j0) = make_float2(fmaf(c2[nt][2], sS2[j0], sT2[j0]),
                                          fmaf(c2[nt][3], sS2[j1], sT2[j1]));
    }
}

// ============================================================================
extern "C" void kernel_launch(void* const* d_in, const int* in_sizes, int n_in,
                              void* d_out, int out_size)
{
    const float* xyz_down  = (const float*)d_in[0];
    const float* xyz_up    = (const float*)d_in[1];
    const float* feat_down = (const float*)d_in[2];
    const float* feat_up   = (const float*)d_in[3];
    const float* W1  = (const float*)d_in[4];
    const float* b1  = (const float*)d_in[5];
    const float* g1  = (const float*)d_in[6];
    const float* be1 = (const float*)d_in[7];
    const float* mu1 = (const float*)d_in[8];
    const float* va1 = (const float*)d_in[9];
    const float* W2  = (const float*)d_in[10];
    const float* b2  = (const float*)d_in[11];
    const float* g2  = (const float*)d_in[12];
    const float* be2 = (const float*)d_in[13];
    const float* mu2 = (const float*)d_in[14];
    const float* va2 = (const float*)d_in[15];
    float* out = (float*)d_out;

    prep_feat<<<dim3(M_ / 64, B_), 256>>>(feat_down);
    prep_w<<<1, 256>>>(W1, b1, g1, be1, mu1, va1, W2, b2, g2, be2, mu2, va2);

    interp_kernel<<<dim3(N_ / 128, B_), 256>>>(xyz_down, xyz_up, feat_up);

    cudaFuncSetAttribute(mlp_kernel,
                         cudaFuncAttributeMaxDynamicSharedMemorySize, MLP_SMEM);
    mlp_kernel<<<(B_ * N_) / 128, 256, MLP_SMEM>>>(out);
}

// round 4
// speedup vs baseline: 3.5940x; 1.0531x over previous
#include <cuda_runtime.h>
#include <cuda_bf16.h>

typedef unsigned int u32;

// Problem constants
constexpr int B_  = 4;
constexpr int M_  = 2048;
constexpr int N_  = 16384;

// ---------------- device scratch ----------------
__device__ float g_ibuf[(size_t)B_ * N_ * 64];                // interp features
__device__ __nv_bfloat16 g_fTh[(size_t)B_ * 64 * M_];         // featT hi (B,64,M)
__device__ __nv_bfloat16 g_fTl[(size_t)B_ * 64 * M_];         // featT lo
__device__ __nv_bfloat16 g_W1h[128 * 128], g_W1l[128 * 128];
__device__ __nv_bfloat16 g_W2h[64 * 128],  g_W2l[64 * 128];
__device__ float g_S1[128], g_T1[128], g_S2[64], g_T2[64];

// ---------------- helpers ----------------
__device__ __forceinline__ u32 smem_u32(const void* p) {
    u32 a;
    asm("{ .reg .u64 t; cvta.to.shared.u64 t, %1; cvt.u32.u64 %0, t; }" : "=r"(a) : "l"(p));
    return a;
}
__device__ __forceinline__ u32 cvt_bf2(float hi, float lo) {
    u32 r;
    asm("cvt.rn.bf16x2.f32 %0, %1, %2;" : "=r"(r) : "f"(hi), "f"(lo));
    return r;
}
__device__ __forceinline__ void ldsm_x2(u32& r0, u32& r1, u32 addr) {
    asm volatile("ldmatrix.sync.aligned.m8n8.x2.shared.b16 {%0, %1}, [%2];"
                 : "=r"(r0), "=r"(r1) : "r"(addr));
}
__device__ __forceinline__ void mma_bf16(float* c, const u32* a, u32 b0, u32 b1) {
    asm volatile(
        "mma.sync.aligned.m16n8k16.row.col.f32.bf16.bf16.f32 "
        "{%0,%1,%2,%3}, {%4,%5,%6,%7}, {%8,%9}, {%0,%1,%2,%3};"
        : "+f"(c[0]), "+f"(c[1]), "+f"(c[2]), "+f"(c[3])
        : "r"(a[0]), "r"(a[1]), "r"(a[2]), "r"(a[3]), "r"(b0), "r"(b1));
}
__device__ __forceinline__ void split_lo(u32 hpack, float f0, float f1, u32& lpack) {
    float e0 = __uint_as_float(hpack << 16);
    float e1 = __uint_as_float(hpack & 0xFFFF0000u);
    lpack = cvt_bf2(f1 - e1, f0 - e0);
}
__device__ __forceinline__ void cp16(u32 dst, const void* src) {
    asm volatile("cp.async.ca.shared.global [%0], [%1], 16;" :: "r"(dst), "l"(src) : "memory");
}
#define CP_COMMIT() asm volatile("cp.async.commit_group;" ::: "memory")
#define CP_WAIT0()  asm volatile("cp.async.wait_group 0;" ::: "memory")

// ============================================================================
// Prep 1: feat_down (B,M,64) f32 -> g_fTh/g_fTl (B,64,M) bf16 hi/lo
// ============================================================================
__global__ __launch_bounds__(256) void prep_feat(const float* __restrict__ feat_down) {
    __shared__ float sT[64][65];
    const int b = blockIdx.y, m0 = blockIdx.x * 64;
    const int tid = threadIdx.x;
#pragma unroll
    for (int j = 0; j < 4; ++j) {
        int i = tid + j * 256;
        int r = i >> 4, c4 = (i & 15) * 4;
        float4 v = *(const float4*)(feat_down + ((size_t)b * M_ + m0 + r) * 64 + c4);
        sT[c4 + 0][r] = v.x; sT[c4 + 1][r] = v.y;
        sT[c4 + 2][r] = v.z; sT[c4 + 3][r] = v.w;
    }
    __syncthreads();
#pragma unroll
    for (int j = 0; j < 8; ++j) {
        int u = tid + j * 256;
        int d = u >> 5, m2 = (u & 31) * 2;
        float f0 = sT[d][m2], f1 = sT[d][m2 + 1];
        u32 hp = cvt_bf2(f1, f0);
        u32 lp; split_lo(hp, f0, f1, lp);
        size_t o = (size_t)(b * 64 + d) * M_ + m0 + m2;
        *(u32*)(g_fTh + o) = hp;
        *(u32*)(g_fTl + o) = lp;
    }
}

// ============================================================================
// Prep 2: split W1/W2 (grid 96x256); block 0 folds BN
// ============================================================================
__global__ __launch_bounds__(256) void prep_w(
    const float* __restrict__ W1, const float* __restrict__ b1,
    const float* __restrict__ g1, const float* __restrict__ be1,
    const float* __restrict__ mu1, const float* __restrict__ va1,
    const float* __restrict__ W2, const float* __restrict__ b2,
    const float* __restrict__ g2, const float* __restrict__ be2,
    const float* __restrict__ mu2, const float* __restrict__ va2)
{
    const int idx = blockIdx.x * 256 + threadIdx.x;
    if (idx < 16384) {
        float w = W1[idx];
        __nv_bfloat16 h = __float2bfloat16_rn(w);
        g_W1h[idx] = h;
        g_W1l[idx] = __float2bfloat16_rn(w - __bfloat162float(h));
    } else {
        int i = idx - 16384;
        float w = W2[i];
        __nv_bfloat16 h = __float2bfloat16_rn(w);
        g_W2h[i] = h;
        g_W2l[i] = __float2bfloat16_rn(w - __bfloat162float(h));
    }
    if (blockIdx.x == 0) {
        int tid = threadIdx.x;
        if (tid < 128) {
            float s = g1[tid] * rsqrtf(va1[tid] + 1e-5f);
            g_S1[tid] = s;
            g_T1[tid] = (b1[tid] - mu1[tid]) * s + be1[tid];
        }
        if (tid < 64) {
            float s = g2[tid] * rsqrtf(va2[tid] + 1e-5f);
            g_S2[tid] = s;
            g_T2[tid] = (b2[tid] - mu2[tid]) * s + be2[tid];
        }
    }
}

// ============================================================================
// Kernel A: interpolation, double-buffered cp.async pipeline.
// grid (N/128, B), 256 threads (8 warps x 16 rows).
// ============================================================================
constexpr int BPITCH = 136;                       // bf16 elems per smem row
constexpr int BTILE  = 64 * BPITCH * 2;           // 17408 B, one (h or l) tile
constexpr int OFF_B0 = 0;                         // [h0][l0]
constexpr int OFF_B1 = 2 * BTILE;                 // [h1][l1]
constexpr int OFF_UP = 4 * BTILE;                 // 69632, float4[128]
constexpr int OFF_D0 = OFF_UP + 2048;             // float4[128]
constexpr int OFF_D1 = OFF_D0 + 2048;
constexpr int OFF_RS = OFF_D1 + 2048;
constexpr int INTERP_SMEM = OFF_RS + 512;         // 76288 B

__global__ __launch_bounds__(256, 2) void interp_kernel(
    const float* __restrict__ xyz_down,
    const float* __restrict__ xyz_up,
    float* __restrict__ dummy)
{
    extern __shared__ __align__(16) char smem[];
    const u32 sbase = smem_u32(smem);

    const int tid = threadIdx.x, wid = tid >> 5, lane = tid & 31;
    const int b = blockIdx.y, n0 = blockIdx.x * 128;
    const int g = lane >> 2, tg = lane & 3;
    const int r0 = wid * 16;

    // ---- stage B tile t into buffer sel via cp.async ----
    auto stageB = [&](int t, int sel) {
        const u32 dstb = sbase + sel * (2 * BTILE);
#pragma unroll
        for (int j = 0; j < 4; ++j) {
            int idx = tid + 256 * j;
            int d = idx >> 4, kc = (idx & 15) * 8;
            size_t go = (size_t)(b * 64 + d) * M_ + t * 128 + kc;
            u32 doff = (u32)(d * (BPITCH * 2) + kc * 2);
            cp16(dstb + doff, g_fTh + go);
            cp16(dstb + BTILE + doff, g_fTl + go);
        }
        CP_COMMIT();
    };
    auto loadD = [&](int t) -> float4 {
        const float* p = xyz_down + ((size_t)b * M_ + t * 128 + tid) * 3;
        float x = p[0], y = p[1], z = p[2];
        return make_float4(x, y, z, x * x + y * y + z * z + 1e-8f);
    };

    // ---- prologue ----
    stageB(0, 0);
    if (tid < 128) {
        const float* p = xyz_up + ((size_t)b * N_ + n0 + tid) * 3;
        float x = p[0], y = p[1], z = p[2];
        *(float4*)(smem + OFF_UP + tid * 16) = make_float4(x, y, z, x * x + y * y + z * z);
    }
    float4 qnxt = make_float4(0.f, 0.f, 0.f, 0.f);
    if (tid < 128) {
        *(float4*)(smem + OFF_D0 + tid * 16) = loadD(0);
        qnxt = loadD(1);
    }
    CP_WAIT0();
    __syncthreads();

    const float4 uA = *(const float4*)(smem + OFF_UP + (r0 + g) * 16);
    const float4 uB = *(const float4*)(smem + OFF_UP + (r0 + 8 + g) * 16);

    float c[8][4];
#pragma unroll
    for (int i = 0; i < 8; ++i)
#pragma unroll
        for (int j = 0; j < 4; ++j) c[i][j] = 0.f;
    float rsA = 0.f, rsB = 0.f;

    const u32 lrow = (u32)(lane & 7) * (BPITCH * 2);
    const u32 lkh  = (u32)((lane >> 3) & 1) * 16;

    for (int t = 0; t < 16; ++t) {
        const int sel = t & 1;
        if (t < 15) {
            stageB(t + 1, sel ^ 1);
            if (tid < 128)
                *(float4*)(smem + OFF_D0 + (sel ^ 1) * 2048 + tid * 16) = qnxt;
        }
        if (t < 14 && tid < 128) qnxt = loadD(t + 2);

        const float4* sD  = (const float4*)(smem + OFF_D0 + sel * 2048);
        const u32 baseBh = sbase + sel * (2 * BTILE);
        const u32 baseBl = baseBh + BTILE;

#pragma unroll
        for (int ks = 0; ks < 8; ++ks) {
            const int kb = ks * 16 + tg * 2;
            float4 q0 = sD[kb], q1 = sD[kb + 1], q2 = sD[kb + 8], q3 = sD[kb + 9];

            float d00 = fmaf(fmaf(uA.z, q0.z, fmaf(uA.y, q0.y, uA.x * q0.x)), -2.f, uA.w + q0.w);
            float d01 = fmaf(fmaf(uA.z, q1.z, fmaf(uA.y, q1.y, uA.x * q1.x)), -2.f, uA.w + q1.w);
            float d02 = fmaf(fmaf(uA.z, q2.z, fmaf(uA.y, q2.y, uA.x * q2.x)), -2.f, uA.w + q2.w);
            float d03 = fmaf(fmaf(uA.z, q3.z, fmaf(uA.y, q3.y, uA.x * q3.x)), -2.f, uA.w + q3.w);
            float d10 = fmaf(fmaf(uB.z, q0.z, fmaf(uB.y, q0.y, uB.x * q0.x)), -2.f, uB.w + q0.w);
            float d11 = fmaf(fmaf(uB.z, q1.z, fmaf(uB.y, q1.y, uB.x * q1.x)), -2.f, uB.w + q1.w);
            float d12 = fmaf(fmaf(uB.z, q2.z, fmaf(uB.y, q2.y, uB.x * q2.x)), -2.f, uB.w + q2.w);
            float d13 = fmaf(fmaf(uB.z, q3.z, fmaf(uB.y, q3.y, uB.x * q3.x)), -2.f, uB.w + q3.w);

            float r00 = __fdividef(1.f, d00), r01 = __fdividef(1.f, d01);
            float r02 = __fdividef(1.f, d02), r03 = __fdividef(1.f, d03);
            float r10 = __fdividef(1.f, d10), r11 = __fdividef(1.f, d11);
            float r12 = __fdividef(1.f, d12), r13 = __fdividef(1.f, d13);

            rsA += (r00 + r01) + (r02 + r03);
            rsB += (r10 + r11) + (r12 + r13);

            u32 ah[4], al[4];
            ah[0] = cvt_bf2(r01, r00); split_lo(ah[0], r00, r01, al[0]);
            ah[1] = cvt_bf2(r11, r10); split_lo(ah[1], r10, r11, al[1]);
            ah[2] = cvt_bf2(r03, r02); split_lo(ah[2], r02, r03, al[2]);
            ah[3] = cvt_bf2(r13, r12); split_lo(ah[3], r12, r13, al[3]);

            const u32 koff = (u32)(ks * 32) + lkh;
#pragma unroll
            for (int nt = 0; nt < 8; ++nt) {
                u32 off = (u32)(nt * 8 * BPITCH * 2) + lrow + koff;
                u32 bh0, bh1, bl0, bl1;
                ldsm_x2(bh0, bh1, baseBh + off);
                ldsm_x2(bl0, bl1, baseBl + off);
                mma_bf16(c[nt], ah, bh0, bh1);
                mma_bf16(c[nt], ah, bl0, bl1);
                mma_bf16(c[nt], al, bh0, bh1);
            }
        }
        if (t < 15) { CP_WAIT0(); __syncthreads(); }
    }

    // rsum quad-reduce (lanes of a quad cover all k)
    rsA += __shfl_xor_sync(0xFFFFFFFFu, rsA, 1);
    rsA += __shfl_xor_sync(0xFFFFFFFFu, rsA, 2);
    rsB += __shfl_xor_sync(0xFFFFFFFFu, rsB, 1);
    rsB += __shfl_xor_sync(0xFFFFFFFFu, rsB, 2);
    if (tg == 0) {
        *(float*)(smem + OFF_RS + (r0 + g) * 4) = rsA;
        *(float*)(smem + OFF_RS + (r0 + 8 + g) * 4) = rsB;
    }
    __syncwarp();

    const float invA = __fdividef(1.f, *(const float*)(smem + OFF_RS + (r0 + g) * 4));
    const float invB = __fdividef(1.f, *(const float*)(smem + OFF_RS + (r0 + 8 + g) * 4));
    float* rowA = g_ibuf + ((size_t)(b * N_ + n0 + r0 + g)) * 64;
    float* rowB = g_ibuf + ((size_t)(b * N_ + n0 + r0 + 8 + g)) * 64;
#pragma unroll
    for (int nt = 0; nt < 8; ++nt) {
        *(float2*)(rowA + nt * 8 + 2 * tg) = make_float2(c[nt][0] * invA, c[nt][1] * invA);
        *(float2*)(rowB + nt * 8 + 2 * tg) = make_float2(c[nt][2] * invB, c[nt][3] * invB);
    }
    (void)dummy;
}

// ============================================================================
// Kernel B: persistent fused tensor MLP. grid 256, 2 row-tiles per CTA.
// x: ch 0-63 from feat_up, ch 64-127 from g_ibuf.
// ============================================================================
constexpr int SMW1 = 128 * BPITCH;
constexpr int SMW2 = 64 * BPITCH;
constexpr int MLP_SMEM = (SMW1 * 2 + SMW2 * 2) * 2 + (128 + 128 + 64 + 64) * 4;
constexpr int NTILES = (B_ * N_) / 128;    // 512

__global__ __launch_bounds__(256) void mlp_kernel(
    const float* __restrict__ feat_up, float* __restrict__ out)
{
    extern __shared__ __align__(16) char sm[];
    __nv_bfloat16* sW1h = (__nv_bfloat16*)sm;
    __nv_bfloat16* sW1l = sW1h + SMW1;
    __nv_bfloat16* sW2h = sW1l + SMW1;
    __nv_bfloat16* sW2l = sW2h + SMW2;
    float* sS1 = (float*)(sW2l + SMW2);
    float* sT1 = sS1 + 128;
    float* sS2 = sT1 + 128;
    float* sT2 = sS2 + 64;

    const int tid = threadIdx.x, wid = tid >> 5, lane = tid & 31;
    const int g = lane >> 2, tg = lane & 3;
    const int r0 = wid * 16;

    for (int i = tid; i < 2048; i += 256) {
        int r = i >> 4, q = (i & 15) * 8;
        *(uint4*)(sW1h + r * BPITCH + q) = ((const uint4*)g_W1h)[i];
        *(uint4*)(sW1l + r * BPITCH + q) = ((const uint4*)g_W1l)[i];
    }
    for (int i = tid; i < 1024; i += 256) {
        int r = i >> 4, q = (i & 15) * 8;
        *(uint4*)(sW2h + r * BPITCH + q) = ((const uint4*)g_W2h)[i];
        *(uint4*)(sW2l + r * BPITCH + q) = ((const uint4*)g_W2l)[i];
    }
    if (tid < 128) { sS1[tid] = g_S1[tid]; sT1[tid] = g_T1[tid]; }
    if (tid < 64)  { sS2[tid] = g_S2[tid]; sT2[tid] = g_T2[tid]; }
    __syncthreads();

    const u32 bW1h = smem_u32(sW1h), bW1l = smem_u32(sW1l);
    const u32 bW2h = smem_u32(sW2h), bW2l = smem_u32(sW2l);
    const u32 lrow = (u32)(lane & 7) * (BPITCH * 2);
    const u32 lkh  = (u32)((lane >> 3) & 1) * 16;

    for (int tile = blockIdx.x; tile < NTILES; tile += gridDim.x) {
        const size_t rowA = (size_t)tile * 128 + r0 + g;
        const size_t rowB = rowA + 8;
        const float* fuA = feat_up + rowA * 64;
        const float* fuB = feat_up + rowB * 64;
        const float* ibA = g_ibuf + rowA * 64;
        const float* ibB = g_ibuf + rowB * 64;

        // ---------------- GEMM1 ----------------
        float c1[16][4];
#pragma unroll
        for (int i = 0; i < 16; ++i)
#pragma unroll
            for (int j = 0; j < 4; ++j) c1[i][j] = 0.f;

#pragma unroll
        for (int ks = 0; ks < 8; ++ks) {
            const float* sA = (ks < 4) ? (fuA + ks * 16) : (ibA + (ks - 4) * 16);
            const float* sB = (ks < 4) ? (fuB + ks * 16) : (ibB + (ks - 4) * 16);
            float2 p0 = *(const float2*)(sA + 2 * tg);
            float2 p1 = *(const float2*)(sA + 2 * tg + 8);
            float2 p2 = *(const float2*)(sB + 2 * tg);
            float2 p3 = *(const float2*)(sB + 2 * tg + 8);
            u32 ah[4], al[4];
            ah[0] = cvt_bf2(p0.y, p0.x); split_lo(ah[0], p0.x, p0.y, al[0]);
            ah[1] = cvt_bf2(p2.y, p2.x); split_lo(ah[1], p2.x, p2.y, al[1]);
            ah[2] = cvt_bf2(p1.y, p1.x); split_lo(ah[2], p1.x, p1.y, al[2]);
            ah[3] = cvt_bf2(p3.y, p3.x); split_lo(ah[3], p3.x, p3.y, al[3]);

            const u32 koff = (u32)(ks * 32) + lkh;
#pragma unroll
            for (int nt = 0; nt < 16; ++nt) {
                u32 off = (u32)(nt * 8 * BPITCH * 2) + lrow + koff;
                u32 bh0, bh1, bl0, bl1;
                ldsm_x2(bh0, bh1, bW1h + off);
                ldsm_x2(bl0, bl1, bW1l + off);
                mma_bf16(c1[nt], ah, bh0, bh1);
                mma_bf16(c1[nt], ah, bl0, bl1);
                mma_bf16(c1[nt], al, bh0, bh1);
            }
        }

        // ---------------- BN1 + relu -> A2 fragments ----------------
        u32 a2h[8][4], a2l[8][4];
#pragma unroll
        for (int k2 = 0; k2 < 8; ++k2) {
            int nt0 = 2 * k2, nt1 = 2 * k2 + 1;
            int o0 = nt0 * 8 + 2 * tg, o1 = o0 + 1;
            int o2 = nt1 * 8 + 2 * tg, o3 = o2 + 1;
            float hA0 = fmaxf(fmaf(c1[nt0][0], sS1[o0], sT1[o0]), 0.f);
            float hA1 = fmaxf(fmaf(c1[nt0][1], sS1[o1], sT1[o1]), 0.f);
            float hB0 = fmaxf(fmaf(c1[nt0][2], sS1[o0], sT1[o0]), 0.f);
            float hB1 = fmaxf(fmaf(c1[nt0][3], sS1[o1], sT1[o1]), 0.f);
            float hA2 = fmaxf(fmaf(c1[nt1][0], sS1[o2], sT1[o2]), 0.f);
            float hA3 = fmaxf(fmaf(c1[nt1][1], sS1[o3], sT1[o3]), 0.f);
            float hB2 = fmaxf(fmaf(c1[nt1][2], sS1[o2], sT1[o2]), 0.f);
            float hB3 = fmaxf(fmaf(c1[nt1][3], sS1[o3], sT1[o3]), 0.f);
            a2h[k2][0] = cvt_bf2(hA1, hA0); split_lo(a2h[k2][0], hA0, hA1, a2l[k2][0]);
            a2h[k2][1] = cvt_bf2(hB1, hB0); split_lo(a2h[k2][1], hB0, hB1, a2l[k2][1]);
            a2h[k2][2] = cvt_bf2(hA3, hA2); split_lo(a2h[k2][2], hA2, hA3, a2l[k2][2]);
            a2h[k2][3] = cvt_bf2(hB3, hB2); split_lo(a2h[k2][3], hB2, hB3, a2l[k2][3]);
        }

        // ---------------- GEMM2 ----------------
        float c2[8][4];
#pragma unroll
        for (int i = 0; i < 8; ++i)
#pragma unroll
            for (int j = 0; j < 4; ++j) c2[i][j] = 0.f;

#pragma unroll
        for (int k2 = 0; k2 < 8; ++k2) {
            const u32 koff = (u32)(k2 * 32) + lkh;
#pragma unroll
            for (int nt = 0; nt < 8; ++nt) {
                u32 off = (u32)(nt * 8 * BPITCH * 2) + lrow + koff;
                u32 bh0, bh1, bl0, bl1;
                ldsm_x2(bh0, bh1, bW2h + off);
                ldsm_x2(bl0, bl1, bW2l + off);
                mma_bf16(c2[nt], a2h[k2], bh0, bh1);
                mma_bf16(c2[nt], a2h[k2], bl0, bl1);
                mma_bf16(c2[nt], a2l[k2], bh0, bh1);
            }
        }

        // ---------------- BN2 + store ----------------
        float* oA = out + rowA * 64;
        float* oB = out + rowB * 64;
#pragma unroll
        for (int nt = 0; nt < 8; ++nt) {
            int j0 = nt * 8 + 2 * tg, j1 = j0 + 1;
            *(float2*)(oA + j0) = make_float2(fmaf(c2[nt][0], sS2[j0], sT2[j0]),
                                              fmaf(c2[nt][1], sS2[j1], sT2[j1]));
            *(float2*)(oB + j0) = make_float2(fmaf(c2[nt][2], sS2[j0], sT2[j0]),
                                              fmaf(c2[nt][3], sS2[j1], sT2[j1]));
        }
    }
}

// ============================================================================
extern "C" void kernel_launch(void* const* d_in, const int* in_sizes, int n_in,
                              void* d_out, int out_size)
{
    const float* xyz_down  = (const float*)d_in[0];
    const float* xyz_up    = (const float*)d_in[1];
    const float* feat_down = (const float*)d_in[2];
    const float* feat_up   = (const float*)d_in[3];
    const float* W1  = (const float*)d_in[4];
    const float* b1  = (const float*)d_in[5];
    const float* g1  = (const float*)d_in[6];
    const float* be1 = (const float*)d_in[7];
    const float* mu1 = (const float*)d_in[8];
    const float* va1 = (const float*)d_in[9];
    const float* W2  = (const float*)d_in[10];
    const float* b2  = (const float*)d_in[11];
    const float* g2  = (const float*)d_in[12];
    const float* be2 = (const float*)d_in[13];
    const float* mu2 = (const float*)d_in[14];
    const float* va2 = (const float*)d_in[15];
    float* out = (float*)d_out;

    prep_feat<<<dim3(M_ / 64, B_), 256>>>(feat_down);
    prep_w<<<96, 256>>>(W1, b1, g1, be1, mu1, va1, W2, b2, g2, be2, mu2, va2);

    cudaFuncSetAttribute(interp_kernel,
                         cudaFuncAttributeMaxDynamicSharedMemorySize, INTERP_SMEM);
    interp_kernel<<<dim3(N_ / 128, B_), 256, INTERP_SMEM>>>(xyz_down, xyz_up, nullptr);

    cudaFuncSetAttribute(mlp_kernel,
                         cudaFuncAttributeMaxDynamicSharedMemorySize, MLP_SMEM);
    mlp_kernel<<<256, 256, MLP_SMEM>>>(feat_up, out);
}

// round 5
// speedup vs baseline: 3.5994x; 1.0015x over previous
#include <cuda_runtime.h>
#include <cuda_bf16.h>

typedef unsigned int u32;

constexpr int B_ = 4;
constexpr int M_ = 2048;
constexpr int N_ = 16384;

// ---------------- device scratch ----------------
__device__ __nv_bfloat16 g_fTh[(size_t)B_ * 64 * M_];   // featT hi (B,64,M)
__device__ __nv_bfloat16 g_fTl[(size_t)B_ * 64 * M_];   // featT lo
__device__ __nv_bfloat16 g_W1h[128 * 128], g_W1l[128 * 128];
__device__ __nv_bfloat16 g_W2h[64 * 128],  g_W2l[64 * 128];
__device__ float g_S1[128], g_T1[128], g_S2[64], g_T2[64];

// ---------------- helpers ----------------
__device__ __forceinline__ u32 smem_u32(const void* p) {
    u32 a;
    asm("{ .reg .u64 t; cvta.to.shared.u64 t, %1; cvt.u32.u64 %0, t; }" : "=r"(a) : "l"(p));
    return a;
}
__device__ __forceinline__ u32 cvt_bf2(float hi, float lo) {
    u32 r;
    asm("cvt.rn.bf16x2.f32 %0, %1, %2;" : "=r"(r) : "f"(hi), "f"(lo));
    return r;
}
__device__ __forceinline__ void split_lo(u32 hpack, float f0, float f1, u32& lpack) {
    float e0 = __uint_as_float(hpack << 16);
    float e1 = __uint_as_float(hpack & 0xFFFF0000u);
    lpack = cvt_bf2(f1 - e1, f0 - e0);
}
// x4: lanes 0-7 -> bh(k0) rows, 8-15 -> bh(k+8), 16-23 -> bl(k0), 24-31 -> bl(k+8)
__device__ __forceinline__ void ldsm_x4(u32* r, u32 addr) {
    asm volatile("ldmatrix.sync.aligned.m8n8.x4.shared.b16 {%0, %1, %2, %3}, [%4];"
                 : "=r"(r[0]), "=r"(r[1]), "=r"(r[2]), "=r"(r[3]) : "r"(addr));
}
__device__ __forceinline__ void mma_bf16(float* c, const u32* a, u32 b0, u32 b1) {
    asm volatile(
        "mma.sync.aligned.m16n8k16.row.col.f32.bf16.bf16.f32 "
        "{%0,%1,%2,%3}, {%4,%5,%6,%7}, {%8,%9}, {%0,%1,%2,%3};"
        : "+f"(c[0]), "+f"(c[1]), "+f"(c[2]), "+f"(c[3])
        : "r"(a[0]), "r"(a[1]), "r"(a[2]), "r"(a[3]), "r"(b0), "r"(b1));
}
__device__ __forceinline__ void cp16(u32 dst, const void* src) {
    asm volatile("cp.async.ca.shared.global [%0], [%1], 16;" :: "r"(dst), "l"(src) : "memory");
}
#define CP_COMMIT() asm volatile("cp.async.commit_group;" ::: "memory")
#define CP_WAIT0()  asm volatile("cp.async.wait_group 0;" ::: "memory")

// ============================================================================
// Prep 1: feat_down (B,M,64) f32 -> g_fTh/g_fTl (B,64,M) bf16 hi/lo
// ============================================================================
__global__ __launch_bounds__(256) void prep_feat(const float* __restrict__ feat_down) {
    __shared__ float sT[64][65];
    const int b = blockIdx.y, m0 = blockIdx.x * 64;
    const int tid = threadIdx.x;
#pragma unroll
    for (int j = 0; j < 4; ++j) {
        int i = tid + j * 256;
        int r = i >> 4, c4 = (i & 15) * 4;
        float4 v = *(const float4*)(feat_down + ((size_t)b * M_ + m0 + r) * 64 + c4);
        sT[c4 + 0][r] = v.x; sT[c4 + 1][r] = v.y;
        sT[c4 + 2][r] = v.z; sT[c4 + 3][r] = v.w;
    }
    __syncthreads();
#pragma unroll
    for (int j = 0; j < 8; ++j) {
        int u = tid + j * 256;
        int d = u >> 5, m2 = (u & 31) * 2;
        float f0 = sT[d][m2], f1 = sT[d][m2 + 1];
        u32 hp = cvt_bf2(f1, f0);
        u32 lp; split_lo(hp, f0, f1, lp);
        size_t o = (size_t)(b * 64 + d) * M_ + m0 + m2;
        *(u32*)(g_fTh + o) = hp;
        *(u32*)(g_fTl + o) = lp;
    }
}

// ============================================================================
// Prep 2: split W1/W2 (grid 96x256); block 0 folds BN
// ============================================================================
__global__ __launch_bounds__(256) void prep_w(
    const float* __restrict__ W1, const float* __restrict__ b1,
    const float* __restrict__ g1, const float* __restrict__ be1,
    const float* __restrict__ mu1, const float* __restrict__ va1,
    const float* __restrict__ W2, const float* __restrict__ b2,
    const float* __restrict__ g2, const float* __restrict__ be2,
    const float* __restrict__ mu2, const float* __restrict__ va2)
{
    const int idx = blockIdx.x * 256 + threadIdx.x;
    if (idx < 16384) {
        float w = W1[idx];
        __nv_bfloat16 h = __float2bfloat16_rn(w);
        g_W1h[idx] = h;
        g_W1l[idx] = __float2bfloat16_rn(w - __bfloat162float(h));
    } else {
        int i = idx - 16384;
        float w = W2[i];
        __nv_bfloat16 h = __float2bfloat16_rn(w);
        g_W2h[i] = h;
        g_W2l[i] = __float2bfloat16_rn(w - __bfloat162float(h));
    }
    if (blockIdx.x == 0) {
        int tid = threadIdx.x;
        if (tid < 128) {
            float s = g1[tid] * rsqrtf(va1[tid] + 1e-5f);
            g_S1[tid] = s;
            g_T1[tid] = (b1[tid] - mu1[tid]) * s + be1[tid];
        }
        if (tid < 64) {
            float s = g2[tid] * rsqrtf(va2[tid] + 1e-5f);
            g_S2[tid] = s;
            g_T2[tid] = (b2[tid] - mu2[tid]) * s + be2[tid];
        }
    }
}

// ============================================================================
// Fused kernel: interp (tensor) -> MLP (tensor), one CTA = 128 rows.
// grid (N/128, B), 256 threads (8 warps x 16 rows), 2 CTAs/SM.
// ============================================================================
constexpr int RPB    = 272;                 // smem row pitch bytes (136 bf16)
constexpr int BT     = 64 * RPB;            // 17408: one 64x128 bf16 tile
constexpr int OFF_B0 = 0;                   // [h | l] = 34816  (later W1h)
constexpr int OFF_B1 = 34816;               // [h | l] = 34816  (later W1l)
constexpr int OFF_W2 = 69632;               // [W2h | W2l] = 34816
constexpr int OFF_UP = 104448;              // float4[128]
constexpr int OFF_D0 = 106496;              // float4[128]
constexpr int OFF_D1 = 108544;              // float4[128]
constexpr int OFF_BN = 110592;              // S1[128] T1[128] S2[64] T2[64]
constexpr int FUSED_SMEM = 112128;

__global__ __launch_bounds__(256, 2) void fused_kernel(
    const float* __restrict__ xyz_down,
    const float* __restrict__ xyz_up,
    const float* __restrict__ feat_up,
    float* __restrict__ out)
{
    extern __shared__ __align__(16) char smem[];
    const u32 sbase = smem_u32(smem);

    const int tid = threadIdx.x, wid = tid >> 5, lane = tid & 31;
    const int b = blockIdx.y, n0 = blockIdx.x * 128;
    const int g = lane >> 2, tg = lane & 3;
    const int r0 = wid * 16;

    float* sS1 = (float*)(smem + OFF_BN);
    float* sT1 = sS1 + 128;
    float* sS2 = sT1 + 128;
    float* sT2 = sS2 + 64;

    // lane offsets for ldmatrix.x4 (hi/lo separation as 4th/3rd matrices)
    const u32 lbase = (u32)((lane & 7) * RPB + ((lane >> 3) & 1) * 16);
    const u32 lsep17 = lbase + (u32)(((lane >> 4) & 1) * BT);       // interp B, W2
    const u32 lsep34 = lbase + (u32)(((lane >> 4) & 1) * 34816);    // W1

    auto stageB = [&](int t, int sel) {
        const u32 dstb = sbase + (u32)(sel * 34816);
#pragma unroll
        for (int j = 0; j < 4; ++j) {
            int idx = tid + 256 * j;
            int d = idx >> 4, kc = (idx & 15) * 8;
            size_t go = (size_t)(b * 64 + d) * M_ + t * 128 + kc;
            u32 doff = (u32)(d * RPB + kc * 2);
            cp16(dstb + doff, g_fTh + go);
            cp16(dstb + BT + doff, g_fTl + go);
        }
        CP_COMMIT();
    };
    auto stageW = [&](const __nv_bfloat16* src, u32 dstoff, int rows) {
        for (int i = tid; i < rows * 16; i += 256) {
            int r = i >> 4, q = i & 15;
            cp16(sbase + dstoff + (u32)(r * RPB + q * 16), src + r * 128 + q * 8);
        }
    };
    auto loadD = [&](int t) -> float4 {
        const float* p = xyz_down + ((size_t)b * M_ + t * 128 + tid) * 3;
        float x = p[0], y = p[1], z = p[2];
        return make_float4(x, y, z, x * x + y * y + z * z + 1e-8f);
    };

    // ---------------- prologue ----------------
    stageB(0, 0);
    stageW(g_W2h, OFF_W2, 64);
    stageW(g_W2l, OFF_W2 + BT, 64);
    CP_COMMIT();
    if (tid < 128) {
        const float* p = xyz_up + ((size_t)b * N_ + n0 + tid) * 3;
        float x = p[0], y = p[1], z = p[2];
        *(float4*)(smem + OFF_UP + tid * 16) = make_float4(x, y, z, x * x + y * y + z * z);
        sS1[tid] = g_S1[tid];
        sT1[tid] = g_T1[tid];
        if (tid < 64) { sS2[tid] = g_S2[tid]; sT2[tid] = g_T2[tid]; }
    }
    float4 qnxt = make_float4(0.f, 0.f, 0.f, 0.f);
    if (tid < 128) {
        *(float4*)(smem + OFF_D0 + tid * 16) = loadD(0);
        qnxt = loadD(1);
    }
    CP_WAIT0();
    __syncthreads();

    const float4 uA = *(const float4*)(smem + OFF_UP + (r0 + g) * 16);
    const float4 uB = *(const float4*)(smem + OFF_UP + (r0 + 8 + g) * 16);

    float c[8][4];
#pragma unroll
    for (int i = 0; i < 8; ++i)
#pragma unroll
        for (int j = 0; j < 4; ++j) c[i][j] = 0.f;
    float rsA = 0.f, rsB = 0.f;

    // ================= Phase 1: interpolation =================
    for (int t = 0; t < 16; ++t) {
        const int sel = t & 1;
        if (t < 15) {
            stageB(t + 1, sel ^ 1);
            if (tid < 128)
                *(float4*)(smem + OFF_D0 + (sel ^ 1) * 2048 + tid * 16) = qnxt;
        } else {
            stageW(g_W1h, OFF_B0, 128);   // B0 retired after tile 14
            CP_COMMIT();
        }
        if (t < 14 && tid < 128) qnxt = loadD(t + 2);

        const float4* sD = (const float4*)(smem + OFF_D0 + sel * 2048);
        const u32 bsel = sbase + (u32)(sel * 34816);

#pragma unroll
        for (int ks = 0; ks < 8; ++ks) {
            const int kb = ks * 16 + tg * 2;
            float4 q0 = sD[kb], q1 = sD[kb + 1], q2 = sD[kb + 8], q3 = sD[kb + 9];

            float d00 = fmaf(fmaf(uA.z, q0.z, fmaf(uA.y, q0.y, uA.x * q0.x)), -2.f, uA.w + q0.w);
            float d01 = fmaf(fmaf(uA.z, q1.z, fmaf(uA.y, q1.y, uA.x * q1.x)), -2.f, uA.w + q1.w);
            float d02 = fmaf(fmaf(uA.z, q2.z, fmaf(uA.y, q2.y, uA.x * q2.x)), -2.f, uA.w + q2.w);
            float d03 = fmaf(fmaf(uA.z, q3.z, fmaf(uA.y, q3.y, uA.x * q3.x)), -2.f, uA.w + q3.w);
            float d10 = fmaf(fmaf(uB.z, q0.z, fmaf(uB.y, q0.y, uB.x * q0.x)), -2.f, uB.w + q0.w);
            float d11 = fmaf(fmaf(uB.z, q1.z, fmaf(uB.y, q1.y, uB.x * q1.x)), -2.f, uB.w + q1.w);
            float d12 = fmaf(fmaf(uB.z, q2.z, fmaf(uB.y, q2.y, uB.x * q2.x)), -2.f, uB.w + q2.w);
            float d13 = fmaf(fmaf(uB.z, q3.z, fmaf(uB.y, q3.y, uB.x * q3.x)), -2.f, uB.w + q3.w);

            float r00 = __fdividef(1.f, d00), r01 = __fdividef(1.f, d01);
            float r02 = __fdividef(1.f, d02), r03 = __fdividef(1.f, d03);
            float r10 = __fdividef(1.f, d10), r11 = __fdividef(1.f, d11);
            float r12 = __fdividef(1.f, d12), r13 = __fdividef(1.f, d13);

            rsA += (r00 + r01) + (r02 + r03);
            rsB += (r10 + r11) + (r12 + r13);

            u32 ah[4], al[4];
            ah[0] = cvt_bf2(r01, r00); split_lo(ah[0], r00, r01, al[0]);
            ah[1] = cvt_bf2(r11, r10); split_lo(ah[1], r10, r11, al[1]);
            ah[2] = cvt_bf2(r03, r02); split_lo(ah[2], r02, r03, al[2]);
            ah[3] = cvt_bf2(r13, r12); split_lo(ah[3], r12, r13, al[3]);

            const u32 baddr = bsel + (u32)(ks * 32) + lsep17;
            u32 bf[8][4];
#pragma unroll
            for (int nt = 0; nt < 8; ++nt) ldsm_x4(bf[nt], baddr + (u32)(nt * 8 * RPB));
#pragma unroll
            for (int nt = 0; nt < 8; ++nt) mma_bf16(c[nt], ah, bf[nt][0], bf[nt][1]);
#pragma unroll
            for (int nt = 0; nt < 8; ++nt) mma_bf16(c[nt], ah, bf[nt][2], bf[nt][3]);
#pragma unroll
            for (int nt = 0; nt < 8; ++nt) mma_bf16(c[nt], al, bf[nt][0], bf[nt][1]);
        }
        if (t < 15) { CP_WAIT0(); __syncthreads(); }
    }

    // rsum quad-reduce; every lane gets its own row sums
    rsA += __shfl_xor_sync(0xFFFFFFFFu, rsA, 1);
    rsA += __shfl_xor_sync(0xFFFFFFFFu, rsA, 2);
    rsB += __shfl_xor_sync(0xFFFFFFFFu, rsB, 1);
    rsB += __shfl_xor_sync(0xFFFFFFFFu, rsB, 2);
    const float invA = __fdividef(1.f, rsA);
    const float invB = __fdividef(1.f, rsB);
#pragma unroll
    for (int nt = 0; nt < 8; ++nt) {
        c[nt][0] *= invA; c[nt][1] *= invA;
        c[nt][2] *= invB; c[nt][3] *= invB;
    }

    // W1l into B1 after ALL warps finished reading tile 15
    __syncthreads();
    stageW(g_W1l, OFF_B1, 128);
    CP_COMMIT();
    CP_WAIT0();
    __syncthreads();

    // ================= Phase 2: fused MLP =================
    const size_t rowA = (size_t)(b * N_ + n0 + r0 + g);
    const size_t rowB = rowA + 8;
    const float* fuA = feat_up + rowA * 64;
    const float* fuB = feat_up + rowB * 64;

    float c1[16][4];
#pragma unroll
    for (int i = 0; i < 16; ++i)
#pragma unroll
        for (int j = 0; j < 4; ++j) c1[i][j] = 0.f;

    // k order: interp channels (ks 4-7) first so c dies early, then feat_up (0-3)
#pragma unroll
    for (int kk = 0; kk < 8; ++kk) {
        const int ks = (kk < 4) ? (kk + 4) : (kk - 4);
        u32 ah[4], al[4];
        if (kk < 4) {
            const int k2 = ks - 4;
            ah[0] = cvt_bf2(c[2*k2][1],   c[2*k2][0]);   split_lo(ah[0], c[2*k2][0],   c[2*k2][1],   al[0]);
            ah[1] = cvt_bf2(c[2*k2][3],   c[2*k2][2]);   split_lo(ah[1], c[2*k2][2],   c[2*k2][3],   al[1]);
            ah[2] = cvt_bf2(c[2*k2+1][1], c[2*k2+1][0]); split_lo(ah[2], c[2*k2+1][0], c[2*k2+1][1], al[2]);
            ah[3] = cvt_bf2(c[2*k2+1][3], c[2*k2+1][2]); split_lo(ah[3], c[2*k2+1][2], c[2*k2+1][3], al[3]);
        } else {
            float2 p0 = *(const float2*)(fuA + ks * 16 + 2 * tg);
            float2 p1 = *(const float2*)(fuA + ks * 16 + 2 * tg + 8);
            float2 p2 = *(const float2*)(fuB + ks * 16 + 2 * tg);
            float2 p3 = *(const float2*)(fuB + ks * 16 + 2 * tg + 8);
            ah[0] = cvt_bf2(p0.y, p0.x); split_lo(ah[0], p0.x, p0.y, al[0]);
            ah[1] = cvt_bf2(p2.y, p2.x); split_lo(ah[1], p2.x, p2.y, al[1]);
            ah[2] = cvt_bf2(p1.y, p1.x); split_lo(ah[2], p1.x, p1.y, al[2]);
            ah[3] = cvt_bf2(p3.y, p3.x); split_lo(ah[3], p3.x, p3.y, al[3]);
        }
        const u32 waddr = sbase + OFF_B0 + (u32)(ks * 32) + lsep34;
#pragma unroll
        for (int grp = 0; grp < 4; ++grp) {
            u32 bf[4][4];
#pragma unroll
            for (int j = 0; j < 4; ++j) ldsm_x4(bf[j], waddr + (u32)((grp * 4 + j) * 8 * RPB));
#pragma unroll
            for (int j = 0; j < 4; ++j) mma_bf16(c1[grp * 4 + j], ah, bf[j][0], bf[j][1]);
#pragma unroll
            for (int j = 0; j < 4; ++j) mma_bf16(c1[grp * 4 + j], ah, bf[j][2], bf[j][3]);
#pragma unroll
            for (int j = 0; j < 4; ++j) mma_bf16(c1[grp * 4 + j], al, bf[j][0], bf[j][1]);
        }
    }

    // BN1 + relu -> A2 fragments
    u32 a2h[8][4], a2l[8][4];
#pragma unroll
    for (int k2 = 0; k2 < 8; ++k2) {
        int nt0 = 2 * k2, nt1 = 2 * k2 + 1;
        int o0 = nt0 * 8 + 2 * tg, o1 = o0 + 1;
        int o2 = nt1 * 8 + 2 * tg, o3 = o2 + 1;
        float hA0 = fmaxf(fmaf(c1[nt0][0], sS1[o0], sT1[o0]), 0.f);
        float hA1 = fmaxf(fmaf(c1[nt0][1], sS1[o1], sT1[o1]), 0.f);
        float hB0 = fmaxf(fmaf(c1[nt0][2], sS1[o0], sT1[o0]), 0.f);
        float hB1 = fmaxf(fmaf(c1[nt0][3], sS1[o1], sT1[o1]), 0.f);
        float hA2 = fmaxf(fmaf(c1[nt1][0], sS1[o2], sT1[o2]), 0.f);
        float hA3 = fmaxf(fmaf(c1[nt1][1], sS1[o3], sT1[o3]), 0.f);
        float hB2 = fmaxf(fmaf(c1[nt1][2], sS1[o2], sT1[o2]), 0.f);
        float hB3 = fmaxf(fmaf(c1[nt1][3], sS1[o3], sT1[o3]), 0.f);
        a2h[k2][0] = cvt_bf2(hA1, hA0); split_lo(a2h[k2][0], hA0, hA1, a2l[k2][0]);
        a2h[k2][1] = cvt_bf2(hB1, hB0); split_lo(a2h[k2][1], hB0, hB1, a2l[k2][1]);
        a2h[k2][2] = cvt_bf2(hA3, hA2); split_lo(a2h[k2][2], hA2, hA3, a2l[k2][2]);
        a2h[k2][3] = cvt_bf2(hB3, hB2); split_lo(a2h[k2][3], hB2, hB3, a2l[k2][3]);
    }

    // GEMM2
    float c2[8][4];
#pragma unroll
    for (int i = 0; i < 8; ++i)
#pragma unroll
        for (int j = 0; j < 4; ++j) c2[i][j] = 0.f;

#pragma unroll
    for (int k2 = 0; k2 < 8; ++k2) {
        const u32 waddr = sbase + OFF_W2 + (u32)(k2 * 32) + lsep17;
#pragma unroll
        for (int grp = 0; grp < 2; ++grp) {
            u32 bf[4][4];
#pragma unroll
            for (int j = 0; j < 4; ++j) ldsm_x4(bf[j], waddr + (u32)((grp * 4 + j) * 8 * RPB));
#pragma unroll
            for (int j = 0; j < 4; ++j) mma_bf16(c2[grp * 4 + j], a2h[k2], bf[j][0], bf[j][1]);
#pragma unroll
            for (int j = 0; j < 4; ++j) mma_bf16(c2[grp * 4 + j], a2h[k2], bf[j][2], bf[j][3]);
#pragma unroll
            for (int j = 0; j < 4; ++j) mma_bf16(c2[grp * 4 + j], a2l[k2], bf[j][0], bf[j][1]);
        }
    }

    // BN2 + store
    float* oA = out + rowA * 64;
    float* oB = out + rowB * 64;
#pragma unroll
    for (int nt = 0; nt < 8; ++nt) {
        int j0 = nt * 8 + 2 * tg, j1 = j0 + 1;
        *(float2*)(oA + j0) = make_float2(fmaf(c2[nt][0], sS2[j0], sT2[j0]),
                                          fmaf(c2[nt][1], sS2[j1], sT2[j1]));
        *(float2*)(oB + j0) = make_float2(fmaf(c2[nt][2], sS2[j0], sT2[j0]),
                                          fmaf(c2[nt][3], sS2[j1], sT2[j1]));
    }
}

// ============================================================================
extern "C" void kernel_launch(void* const* d_in, const int* in_sizes, int n_in,
                              void* d_out, int out_size)
{
    const float* xyz_down  = (const float*)d_in[0];
    const float* xyz_up    = (const float*)d_in[1];
    const float* feat_down = (const float*)d_in[2];
    const float* feat_up   = (const float*)d_in[3];
    const float* W1  = (const float*)d_in[4];
    const float* b1  = (const float*)d_in[5];
    const float* g1  = (const float*)d_in[6];
    const float* be1 = (const float*)d_in[7];
    const float* mu1 = (const float*)d_in[8];
    const float* va1 = (const float*)d_in[9];
    const float* W2  = (const float*)d_in[10];
    const float* b2  = (const float*)d_in[11];
    const float* g2  = (const float*)d_in[12];
    const float* be2 = (const float*)d_in[13];
    const float* mu2 = (const float*)d_in[14];
    const float* va2 = (const float*)d_in[15];
    float* out = (float*)d_out;

    prep_feat<<<dim3(M_ / 64, B_), 256>>>(feat_down);
    prep_w<<<96, 256>>>(W1, b1, g1, be1, mu1, va1, W2, b2, g2, be2, mu2, va2);

    cudaFuncSetAttribute(fused_kernel,
                         cudaFuncAttributeMaxDynamicSharedMemorySize, FUSED_SMEM);
    fused_kernel<<<dim3(N_ / 128, B_), 256, FUSED_SMEM>>>(
        xyz_down, xyz_up, feat_up, out);
}

// round 6
// speedup vs baseline: 4.3643x; 1.2125x over previous
#include <cuda_runtime.h>
#include <cuda_bf16.h>
#include <cuda_fp16.h>

typedef unsigned int u32;

constexpr int B_ = 4;
constexpr int M_ = 2048;
constexpr int N_ = 16384;

// coordinate scale: d' = 256*d, r' = r/256; w = r/Σr invariant
constexpr float CSC  = 16.0f;
constexpr float EPS2 = 2.56e-6f;   // 1e-8 * 256

// ---------------- device scratch ----------------
__device__ float g_ibuf[(size_t)B_ * N_ * 64];           // interp features
__device__ __half g_fTh[(size_t)B_ * 64 * M_];           // featT hi fp16 (B,64,M)
__device__ __half g_fTl[(size_t)B_ * 64 * M_];           // featT lo fp16
__device__ __nv_bfloat16 g_W1h[128 * 128], g_W1l[128 * 128];
__device__ __nv_bfloat16 g_W2h[64 * 128],  g_W2l[64 * 128];
__device__ float g_S1[128], g_T1[128], g_S2[64], g_T2[64];

// ---------------- helpers ----------------
__device__ __forceinline__ u32 smem_u32(const void* p) {
    u32 a;
    asm("{ .reg .u64 t; cvta.to.shared.u64 t, %1; cvt.u32.u64 %0, t; }" : "=r"(a) : "l"(p));
    return a;
}
__device__ __forceinline__ u32 cvt_bf2(float hi, float lo) {
    u32 r;
    asm("cvt.rn.bf16x2.f32 %0, %1, %2;" : "=r"(r) : "f"(hi), "f"(lo));
    return r;
}
__device__ __forceinline__ u32 cvt_h2(float hi, float lo) {
    u32 r;
    asm("cvt.rn.f16x2.f32 %0, %1, %2;" : "=r"(r) : "f"(hi), "f"(lo));
    return r;
}
__device__ __forceinline__ void split_lo(u32 hpack, float f0, float f1, u32& lpack) {
    float e0 = __uint_as_float(hpack << 16);
    float e1 = __uint_as_float(hpack & 0xFFFF0000u);
    lpack = cvt_bf2(f1 - e1, f0 - e0);
}
__device__ __forceinline__ void ldsm_x4(u32* r, u32 addr) {
    asm volatile("ldmatrix.sync.aligned.m8n8.x4.shared.b16 {%0, %1, %2, %3}, [%4];"
                 : "=r"(r[0]), "=r"(r[1]), "=r"(r[2]), "=r"(r[3]) : "r"(addr));
}
__device__ __forceinline__ void mma_bf16(float* c, const u32* a, u32 b0, u32 b1) {
    asm volatile(
        "mma.sync.aligned.m16n8k16.row.col.f32.bf16.bf16.f32 "
        "{%0,%1,%2,%3}, {%4,%5,%6,%7}, {%8,%9}, {%0,%1,%2,%3};"
        : "+f"(c[0]), "+f"(c[1]), "+f"(c[2]), "+f"(c[3])
        : "r"(a[0]), "r"(a[1]), "r"(a[2]), "r"(a[3]), "r"(b0), "r"(b1));
}
__device__ __forceinline__ void mma_f16(float* c, const u32* a, u32 b0, u32 b1) {
    asm volatile(
        "mma.sync.aligned.m16n8k16.row.col.f32.f16.f16.f32 "
        "{%0,%1,%2,%3}, {%4,%5,%6,%7}, {%8,%9}, {%0,%1,%2,%3};"
        : "+f"(c[0]), "+f"(c[1]), "+f"(c[2]), "+f"(c[3])
        : "r"(a[0]), "r"(a[1]), "r"(a[2]), "r"(a[3]), "r"(b0), "r"(b1));
}
__device__ __forceinline__ void cp16(u32 dst, const void* src) {
    asm volatile("cp.async.ca.shared.global [%0], [%1], 16;" :: "r"(dst), "l"(src) : "memory");
}
#define CP_COMMIT() asm volatile("cp.async.commit_group;" ::: "memory")
#define CP_WAIT0()  asm volatile("cp.async.wait_group 0;" ::: "memory")

// ============================================================================
// Prep 1: feat_down (B,M,64) f32 -> g_fTh/g_fTl (B,64,M) fp16 hi/lo
// ============================================================================
__global__ __launch_bounds__(256) void prep_feat(const float* __restrict__ feat_down) {
    __shared__ float sT[64][65];
    const int b = blockIdx.y, m0 = blockIdx.x * 64;
    const int tid = threadIdx.x;
#pragma unroll
    for (int j = 0; j < 4; ++j) {
        int i = tid + j * 256;
        int r = i >> 4, c4 = (i & 15) * 4;
        float4 v = *(const float4*)(feat_down + ((size_t)b * M_ + m0 + r) * 64 + c4);
        sT[c4 + 0][r] = v.x; sT[c4 + 1][r] = v.y;
        sT[c4 + 2][r] = v.z; sT[c4 + 3][r] = v.w;
    }
    __syncthreads();
#pragma unroll
    for (int j = 0; j < 8; ++j) {
        int u = tid + j * 256;
        int d = u >> 5, m2 = (u & 31) * 2;
        float f0 = sT[d][m2], f1 = sT[d][m2 + 1];
        float h0 = __half2float(__float2half_rn(f0));
        float h1 = __half2float(__float2half_rn(f1));
        u32 hp = cvt_h2(f1, f0);
        u32 lp = cvt_h2(f1 - h1, f0 - h0);
        size_t o = (size_t)(b * 64 + d) * M_ + m0 + m2;
        *(u32*)(g_fTh + o) = hp;
        *(u32*)(g_fTl + o) = lp;
    }
}

// ============================================================================
// Prep 2: split W1/W2 to bf16 hi/lo (grid 96x256); block 0 folds BN
// ============================================================================
__global__ __launch_bounds__(256) void prep_w(
    const float* __restrict__ W1, const float* __restrict__ b1,
    const float* __restrict__ g1, const float* __restrict__ be1,
    const float* __restrict__ mu1, const float* __restrict__ va1,
    const float* __restrict__ W2, const float* __restrict__ b2,
    const float* __restrict__ g2, const float* __restrict__ be2,
    const float* __restrict__ mu2, const float* __restrict__ va2)
{
    const int idx = blockIdx.x * 256 + threadIdx.x;
    if (idx < 16384) {
        float w = W1[idx];
        __nv_bfloat16 h = __float2bfloat16_rn(w);
        g_W1h[idx] = h;
        g_W1l[idx] = __float2bfloat16_rn(w - __bfloat162float(h));
    } else {
        int i = idx - 16384;
        float w = W2[i];
        __nv_bfloat16 h = __float2bfloat16_rn(w);
        g_W2h[i] = h;
        g_W2l[i] = __float2bfloat16_rn(w - __bfloat162float(h));
    }
    if (blockIdx.x == 0) {
        int tid = threadIdx.x;
        if (tid < 128) {
            float s = g1[tid] * rsqrtf(va1[tid] + 1e-5f);
            g_S1[tid] = s;
            g_T1[tid] = (b1[tid] - mu1[tid]) * s + be1[tid];
        }
        if (tid < 64) {
            float s = g2[tid] * rsqrtf(va2[tid] + 1e-5f);
            g_S2[tid] = s;
            g_T2[tid] = (b2[tid] - mu2[tid]) * s + be2[tid];
        }
    }
}

// ============================================================================
// Kernel A: interpolation, fp16 r x fp16 feat(hi/lo), 2 MMAs per k-step.
// grid (N/128, B), 256 threads (8 warps x 16 rows), double-buffered cp.async.
// ============================================================================
constexpr int RPB    = 272;                 // smem row pitch bytes (136 halves)
constexpr int BT     = 64 * RPB;            // 17408: one 64x128 fp16 tile
constexpr int OFF_UP = 4 * BT;              // 69632, float4[128]
constexpr int OFF_D0 = OFF_UP + 2048;
constexpr int OFF_D1 = OFF_D0 + 2048;
constexpr int OFF_RS = OFF_D1 + 2048;
constexpr int INTERP_SMEM = OFF_RS + 512;   // 76288 B

__global__ __launch_bounds__(256, 2) void interp_kernel(
    const float* __restrict__ xyz_down,
    const float* __restrict__ xyz_up)
{
    extern __shared__ __align__(16) char smem[];
    const u32 sbase = smem_u32(smem);

    const int tid = threadIdx.x, wid = tid >> 5, lane = tid & 31;
    const int b = blockIdx.y, n0 = blockIdx.x * 128;
    const int g = lane >> 2, tg = lane & 3;
    const int r0 = wid * 16;

    auto stageB = [&](int t, int sel) {
        const u32 dstb = sbase + (u32)(sel * (2 * BT));
#pragma unroll
        for (int j = 0; j < 4; ++j) {
            int idx = tid + 256 * j;
            int d = idx >> 4, kc = (idx & 15) * 8;
            size_t go = (size_t)(b * 64 + d) * M_ + t * 128 + kc;
            u32 doff = (u32)(d * RPB + kc * 2);
            cp16(dstb + doff, g_fTh + go);
            cp16(dstb + BT + doff, g_fTl + go);
        }
        CP_COMMIT();
    };
    auto loadD = [&](int t) -> float4 {
        const float* p = xyz_down + ((size_t)b * M_ + t * 128 + tid) * 3;
        float x = p[0] * CSC, y = p[1] * CSC, z = p[2] * CSC;
        return make_float4(x, y, z, x * x + y * y + z * z + EPS2);
    };

    // ---- prologue ----
    stageB(0, 0);
    if (tid < 128) {
        const float* p = xyz_up + ((size_t)b * N_ + n0 + tid) * 3;
        float x = p[0] * CSC, y = p[1] * CSC, z = p[2] * CSC;
        *(float4*)(smem + OFF_UP + tid * 16) = make_float4(x, y, z, x * x + y * y + z * z);
    }
    float4 qnxt = make_float4(0.f, 0.f, 0.f, 0.f);
    if (tid < 128) {
        *(float4*)(smem + OFF_D0 + tid * 16) = loadD(0);
        qnxt = loadD(1);
    }
    CP_WAIT0();
    __syncthreads();

    const float4 uA = *(const float4*)(smem + OFF_UP + (r0 + g) * 16);
    const float4 uB = *(const float4*)(smem + OFF_UP + (r0 + 8 + g) * 16);

    float c[8][4];
#pragma unroll
    for (int i = 0; i < 8; ++i)
#pragma unroll
        for (int j = 0; j < 4; ++j) c[i][j] = 0.f;
    float rsA = 0.f, rsB = 0.f;

    // ldmatrix.x4 lane addressing: lanes 0-15 -> hi tile rows, 16-31 -> lo tile
    const u32 lbase = (u32)((lane & 7) * RPB + ((lane >> 3) & 1) * 16)
                    + (u32)(((lane >> 4) & 1) * BT);

    for (int t = 0; t < 16; ++t) {
        const int sel = t & 1;
        if (t < 15) {
            stageB(t + 1, sel ^ 1);
            if (tid < 128)
                *(float4*)(smem + OFF_D0 + (sel ^ 1) * 2048 + tid * 16) = qnxt;
        }
        if (t < 14 && tid < 128) qnxt = loadD(t + 2);

        const float4* sD = (const float4*)(smem + OFF_D0 + sel * 2048);
        const u32 bsel = sbase + (u32)(sel * (2 * BT));

#pragma unroll
        for (int ks = 0; ks < 8; ++ks) {
            const int kb = ks * 16 + tg * 2;
            float4 q0 = sD[kb], q1 = sD[kb + 1], q2 = sD[kb + 8], q3 = sD[kb + 9];

            float d00 = fmaf(fmaf(uA.z, q0.z, fmaf(uA.y, q0.y, uA.x * q0.x)), -2.f, uA.w + q0.w);
            float d01 = fmaf(fmaf(uA.z, q1.z, fmaf(uA.y, q1.y, uA.x * q1.x)), -2.f, uA.w + q1.w);
            float d02 = fmaf(fmaf(uA.z, q2.z, fmaf(uA.y, q2.y, uA.x * q2.x)), -2.f, uA.w + q2.w);
            float d03 = fmaf(fmaf(uA.z, q3.z, fmaf(uA.y, q3.y, uA.x * q3.x)), -2.f, uA.w + q3.w);
            float d10 = fmaf(fmaf(uB.z, q0.z, fmaf(uB.y, q0.y, uB.x * q0.x)), -2.f, uB.w + q0.w);
            float d11 = fmaf(fmaf(uB.z, q1.z, fmaf(uB.y, q1.y, uB.x * q1.x)), -2.f, uB.w + q1.w);
            float d12 = fmaf(fmaf(uB.z, q2.z, fmaf(uB.y, q2.y, uB.x * q2.x)), -2.f, uB.w + q2.w);
            float d13 = fmaf(fmaf(uB.z, q3.z, fmaf(uB.y, q3.y, uB.x * q3.x)), -2.f, uB.w + q3.w);

            // r' = 1/d' (scaled), clamped to fp16-safe range
            float r00 = fminf(__fdividef(1.f, d00), 60000.f);
            float r01 = fminf(__fdividef(1.f, d01), 60000.f);
            float r02 = fminf(__fdividef(1.f, d02), 60000.f);
            float r03 = fminf(__fdividef(1.f, d03), 60000.f);
            float r10 = fminf(__fdividef(1.f, d10), 60000.f);
            float r11 = fminf(__fdividef(1.f, d11), 60000.f);
            float r12 = fminf(__fdividef(1.f, d12), 60000.f);
            float r13 = fminf(__fdividef(1.f, d13), 60000.f);

            rsA += (r00 + r01) + (r02 + r03);
            rsB += (r10 + r11) + (r12 + r13);

            u32 ah[4];
            ah[0] = cvt_h2(r01, r00);
            ah[1] = cvt_h2(r11, r10);
            ah[2] = cvt_h2(r03, r02);
            ah[3] = cvt_h2(r13, r12);

            const u32 baddr = bsel + (u32)(ks * 32) + lbase;
            u32 bf[8][4];
#pragma unroll
            for (int nt = 0; nt < 8; ++nt) ldsm_x4(bf[nt], baddr + (u32)(nt * 8 * RPB));
#pragma unroll
            for (int nt = 0; nt < 8; ++nt) mma_f16(c[nt], ah, bf[nt][0], bf[nt][1]);
#pragma unroll
            for (int nt = 0; nt < 8; ++nt) mma_f16(c[nt], ah, bf[nt][2], bf[nt][3]);
        }
        if (t < 15) { CP_WAIT0(); __syncthreads(); }
    }

    // rsum quad-reduce; every lane gets both of its rows' sums
    rsA += __shfl_xor_sync(0xFFFFFFFFu, rsA, 1);
    rsA += __shfl_xor_sync(0xFFFFFFFFu, rsA, 2);
    rsB += __shfl_xor_sync(0xFFFFFFFFu, rsB, 1);
    rsB += __shfl_xor_sync(0xFFFFFFFFu, rsB, 2);
    const float invA = __fdividef(1.f, rsA);
    const float invB = __fdividef(1.f, rsB);

    float* rowA = g_ibuf + ((size_t)(b * N_ + n0 + r0 + g)) * 64;
    float* rowB = g_ibuf + ((size_t)(b * N_ + n0 + r0 + 8 + g)) * 64;
#pragma unroll
    for (int nt = 0; nt < 8; ++nt) {
        *(float2*)(rowA + nt * 8 + 2 * tg) = make_float2(c[nt][0] * invA, c[nt][1] * invA);
        *(float2*)(rowB + nt * 8 + 2 * tg) = make_float2(c[nt][2] * invB, c[nt][3] * invB);
    }
}

// ============================================================================
// Kernel B: persistent fused tensor MLP (unchanged from R4 — known good).
// grid 256, 2 row-tiles per CTA. x: ch 0-63 feat_up, ch 64-127 g_ibuf.
// ============================================================================
constexpr int SMW1 = 128 * 136;
constexpr int SMW2 = 64 * 136;
constexpr int MLP_SMEM = (SMW1 * 2 + SMW2 * 2) * 2 + (128 + 128 + 64 + 64) * 4;
constexpr int NTILES = (B_ * N_) / 128;    // 512

__global__ __launch_bounds__(256) void mlp_kernel(
    const float* __restrict__ feat_up, float* __restrict__ out)
{
    extern __shared__ __align__(16) char sm[];
    __nv_bfloat16* sW1h = (__nv_bfloat16*)sm;
    __nv_bfloat16* sW1l = sW1h + SMW1;
    __nv_bfloat16* sW2h = sW1l + SMW1;
    __nv_bfloat16* sW2l = sW2h + SMW2;
    float* sS1 = (float*)(sW2l + SMW2);
    float* sT1 = sS1 + 128;
    float* sS2 = sT1 + 128;
    float* sT2 = sS2 + 64;

    const int tid = threadIdx.x, wid = tid >> 5, lane = tid & 31;
    const int g = lane >> 2, tg = lane & 3;
    const int r0 = wid * 16;

    for (int i = tid; i < 2048; i += 256) {
        int r = i >> 4, q = (i & 15) * 8;
        *(uint4*)(sW1h + r * 136 + q) = ((const uint4*)g_W1h)[i];
        *(uint4*)(sW1l + r * 136 + q) = ((const uint4*)g_W1l)[i];
    }
    for (int i = tid; i < 1024; i += 256) {
        int r = i >> 4, q = (i & 15) * 8;
        *(uint4*)(sW2h + r * 136 + q) = ((const uint4*)g_W2h)[i];
        *(uint4*)(sW2l + r * 136 + q) = ((const uint4*)g_W2l)[i];
    }
    if (tid < 128) { sS1[tid] = g_S1[tid]; sT1[tid] = g_T1[tid]; }
    if (tid < 64)  { sS2[tid] = g_S2[tid]; sT2[tid] = g_T2[tid]; }
    __syncthreads();

    const u32 bW1h = smem_u32(sW1h), bW1l = smem_u32(sW1l);
    const u32 bW2h = smem_u32(sW2h), bW2l = smem_u32(sW2l);
    const u32 lrow = (u32)(lane & 7) * 272;
    const u32 lkh  = (u32)((lane >> 3) & 1) * 16;

    for (int tile = blockIdx.x; tile < NTILES; tile += gridDim.x) {
        const size_t rowA = (size_t)tile * 128 + r0 + g;
        const size_t rowB = rowA + 8;
        const float* fuA = feat_up + rowA * 64;
        const float* fuB = feat_up + rowB * 64;
        const float* ibA = g_ibuf + rowA * 64;
        const float* ibB = g_ibuf + rowB * 64;

        float c1[16][4];
#pragma unroll
        for (int i = 0; i < 16; ++i)
#pragma unroll
            for (int j = 0; j < 4; ++j) c1[i][j] = 0.f;

#pragma unroll
        for (int ks = 0; ks < 8; ++ks) {
            const float* sA = (ks < 4) ? (fuA + ks * 16) : (ibA + (ks - 4) * 16);
            const float* sB = (ks < 4) ? (fuB + ks * 16) : (ibB + (ks - 4) * 16);
            float2 p0 = *(const float2*)(sA + 2 * tg);
            float2 p1 = *(const float2*)(sA + 2 * tg + 8);
            float2 p2 = *(const float2*)(sB + 2 * tg);
            float2 p3 = *(const float2*)(sB + 2 * tg + 8);
            u32 ah[4], al[4];
            ah[0] = cvt_bf2(p0.y, p0.x); split_lo(ah[0], p0.x, p0.y, al[0]);
            ah[1] = cvt_bf2(p2.y, p2.x); split_lo(ah[1], p2.x, p2.y, al[1]);
            ah[2] = cvt_bf2(p1.y, p1.x); split_lo(ah[2], p1.x, p1.y, al[2]);
            ah[3] = cvt_bf2(p3.y, p3.x); split_lo(ah[3], p3.x, p3.y, al[3]);

            const u32 koff = (u32)(ks * 32) + lkh;
#pragma unroll
            for (int nt = 0; nt < 16; ++nt) {
                u32 off = (u32)(nt * 8 * 272) + lrow + koff;
                u32 bh0, bh1, bl0, bl1;
                asm volatile("ldmatrix.sync.aligned.m8n8.x2.shared.b16 {%0, %1}, [%2];"
                             : "=r"(bh0), "=r"(bh1) : "r"(bW1h + off));
                asm volatile("ldmatrix.sync.aligned.m8n8.x2.shared.b16 {%0, %1}, [%2];"
                             : "=r"(bl0), "=r"(bl1) : "r"(bW1l + off));
                mma_bf16(c1[nt], ah, bh0, bh1);
                mma_bf16(c1[nt], ah, bl0, bl1);
                mma_bf16(c1[nt], al, bh0, bh1);
            }
        }

        u32 a2h[8][4], a2l[8][4];
#pragma unroll
        for (int k2 = 0; k2 < 8; ++k2) {
            int nt0 = 2 * k2, nt1 = 2 * k2 + 1;
            int o0 = nt0 * 8 + 2 * tg, o1 = o0 + 1;
            int o2 = nt1 * 8 + 2 * tg, o3 = o2 + 1;
            float hA0 = fmaxf(fmaf(c1[nt0][0], sS1[o0], sT1[o0]), 0.f);
            float hA1 = fmaxf(fmaf(c1[nt0][1], sS1[o1], sT1[o1]), 0.f);
            float hB0 = fmaxf(fmaf(c1[nt0][2], sS1[o0], sT1[o0]), 0.f);
            float hB1 = fmaxf(fmaf(c1[nt0][3], sS1[o1], sT1[o1]), 0.f);
            float hA2 = fmaxf(fmaf(c1[nt1][0], sS1[o2], sT1[o2]), 0.f);
            float hA3 = fmaxf(fmaf(c1[nt1][1], sS1[o3], sT1[o3]), 0.f);
            float hB2 = fmaxf(fmaf(c1[nt1][2], sS1[o2], sT1[o2]), 0.f);
            float hB3 = fmaxf(fmaf(c1[nt1][3], sS1[o3], sT1[o3]), 0.f);
            a2h[k2][0] = cvt_bf2(hA1, hA0); split_lo(a2h[k2][0], hA0, hA1, a2l[k2][0]);
            a2h[k2][1] = cvt_bf2(hB1, hB0); split_lo(a2h[k2][1], hB0, hB1, a2l[k2][1]);
            a2h[k2][2] = cvt_bf2(hA3, hA2); split_lo(a2h[k2][2], hA2, hA3, a2l[k2][2]);
            a2h[k2][3] = cvt_bf2(hB3, hB2); split_lo(a2h[k2][3], hB2, hB3, a2l[k2][3]);
        }

        float c2[8][4];
#pragma unroll
        for (int i = 0; i < 8; ++i)
#pragma unroll
            for (int j = 0; j < 4; ++j) c2[i][j] = 0.f;

#pragma unroll
        for (int k2 = 0; k2 < 8; ++k2) {
            const u32 koff = (u32)(k2 * 32) + lkh;
#pragma unroll
            for (int nt = 0; nt < 8; ++nt) {
                u32 off = (u32)(nt * 8 * 272) + lrow + koff;
                u32 bh0, bh1, bl0, bl1;
                asm volatile("ldmatrix.sync.aligned.m8n8.x2.shared.b16 {%0, %1}, [%2];"
                             : "=r"(bh0), "=r"(bh1) : "r"(bW2h + off));
                asm volatile("ldmatrix.sync.aligned.m8n8.x2.shared.b16 {%0, %1}, [%2];"
                             : "=r"(bl0), "=r"(bl1) : "r"(bW2l + off));
                mma_bf16(c2[nt], a2h[k2], bh0, bh1);
                mma_bf16(c2[nt], a2h[k2], bl0, bl1);
                mma_bf16(c2[nt], a2l[k2], bh0, bh1);
            }
        }

        float* oA = out + rowA * 64;
        float* oB = out + rowB * 64;
#pragma unroll
        for (int nt = 0; nt < 8; ++nt) {
            int j0 = nt * 8 + 2 * tg, j1 = j0 + 1;
            *(float2*)(oA + j0) = make_float2(fmaf(c2[nt][0], sS2[j0], sT2[j0]),
                                              fmaf(c2[nt][1], sS2[j1], sT2[j1]));
            *(float2*)(oB + j0) = make_float2(fmaf(c2[nt][2], sS2[j0], sT2[j0]),
                                              fmaf(c2[nt][3], sS2[j1], sT2[j1]));
        }
    }
}

// ============================================================================
extern "C" void kernel_launch(void* const* d_in, const int* in_sizes, int n_in,
                              void* d_out, int out_size)
{
    const float* xyz_down  = (const float*)d_in[0];
    const float* xyz_up    = (const float*)d_in[1];
    const float* feat_down = (const float*)d_in[2];
    const float* feat_up   = (const float*)d_in[3];
    const float* W1  = (const float*)d_in[4];
    const float* b1  = (const float*)d_in[5];
    const float* g1  = (const float*)d_in[6];
    const float* be1 = (const float*)d_in[7];
    const float* mu1 = (const float*)d_in[8];
    const float* va1 = (const float*)d_in[9];
    const float* W2  = (const float*)d_in[10];
    const float* b2  = (const float*)d_in[11];
    const float* g2  = (const float*)d_in[12];
    const float* be2 = (const float*)d_in[13];
    const float* mu2 = (const float*)d_in[14];
    const float* va2 = (const float*)d_in[15];
    float* out = (float*)d_out;

    prep_feat<<<dim3(M_ / 64, B_), 256>>>(feat_down);
    prep_w<<<96, 256>>>(W1, b1, g1, be1, mu1, va1, W2, b2, g2, be2, mu2, va2);

    cudaFuncSetAttribute(interp_kernel,
                         cudaFuncAttributeMaxDynamicSharedMemorySize, INTERP_SMEM);
    interp_kernel<<<dim3(N_ / 128, B_), 256, INTERP_SMEM>>>(xyz_down, xyz_up);

    cudaFuncSetAttribute(mlp_kernel,
                         cudaFuncAttributeMaxDynamicSharedMemorySize, MLP_SMEM);
    mlp_kernel<<<256, 256, MLP_SMEM>>>(feat_up, out);
}

// round 7
// speedup vs baseline: 6.2361x; 1.4289x over previous
#include <cuda_runtime.h>
#include <cuda_bf16.h>
#include <cuda_fp16.h>

typedef unsigned int u32;

constexpr int B_ = 4;
constexpr int M_ = 2048;
constexpr int N_ = 16384;

// coordinate scale: d' = 256*d, r' = r/256; w = r/Σr invariant
constexpr float CSC  = 16.0f;
constexpr float EPS2 = 2.56e-6f;   // 1e-8 * 256

// ---------------- device scratch ----------------
__device__ float g_ibuf[(size_t)B_ * N_ * 64];     // interp features
__device__ __half g_fTh[(size_t)B_ * 64 * M_];     // featT fp16 (B,64,M)
__device__ __half g_W1[128 * 128];                 // fp16 weights
__device__ __half g_W2[64 * 128];
__device__ float g_S1[128], g_T1[128], g_S2[64], g_T2[64];

// ---------------- helpers ----------------
__device__ __forceinline__ u32 smem_u32(const void* p) {
    u32 a;
    asm("{ .reg .u64 t; cvta.to.shared.u64 t, %1; cvt.u32.u64 %0, t; }" : "=r"(a) : "l"(p));
    return a;
}
__device__ __forceinline__ u32 cvt_h2(float hi, float lo) {
    u32 r;
    asm("cvt.rn.f16x2.f32 %0, %1, %2;" : "=r"(r) : "f"(hi), "f"(lo));
    return r;
}
__device__ __forceinline__ void ldsm_x4(u32* r, u32 addr) {
    asm volatile("ldmatrix.sync.aligned.m8n8.x4.shared.b16 {%0, %1, %2, %3}, [%4];"
                 : "=r"(r[0]), "=r"(r[1]), "=r"(r[2]), "=r"(r[3]) : "r"(addr));
}
__device__ __forceinline__ void mma_f16(float* c, const u32* a, u32 b0, u32 b1) {
    asm volatile(
        "mma.sync.aligned.m16n8k16.row.col.f32.f16.f16.f32 "
        "{%0,%1,%2,%3}, {%4,%5,%6,%7}, {%8,%9}, {%0,%1,%2,%3};"
        : "+f"(c[0]), "+f"(c[1]), "+f"(c[2]), "+f"(c[3])
        : "r"(a[0]), "r"(a[1]), "r"(a[2]), "r"(a[3]), "r"(b0), "r"(b1));
}
__device__ __forceinline__ void cp16(u32 dst, const void* src) {
    asm volatile("cp.async.ca.shared.global [%0], [%1], 16;" :: "r"(dst), "l"(src) : "memory");
}
#define CP_COMMIT() asm volatile("cp.async.commit_group;" ::: "memory")
#define CP_WAIT0()  asm volatile("cp.async.wait_group 0;" ::: "memory")

// ============================================================================
// Prep 1: feat_down (B,M,64) f32 -> g_fTh (B,64,M) fp16
// ============================================================================
__global__ __launch_bounds__(256) void prep_feat(const float* __restrict__ feat_down) {
    __shared__ float sT[64][65];
    const int b = blockIdx.y, m0 = blockIdx.x * 64;
    const int tid = threadIdx.x;
#pragma unroll
    for (int j = 0; j < 4; ++j) {
        int i = tid + j * 256;
        int r = i >> 4, c4 = (i & 15) * 4;
        float4 v = *(const float4*)(feat_down + ((size_t)b * M_ + m0 + r) * 64 + c4);
        sT[c4 + 0][r] = v.x; sT[c4 + 1][r] = v.y;
        sT[c4 + 2][r] = v.z; sT[c4 + 3][r] = v.w;
    }
    __syncthreads();
#pragma unroll
    for (int j = 0; j < 8; ++j) {
        int u = tid + j * 256;
        int d = u >> 5, m2 = (u & 31) * 2;
        size_t o = (size_t)(b * 64 + d) * M_ + m0 + m2;
        *(u32*)(g_fTh + o) = cvt_h2(sT[d][m2 + 1], sT[d][m2]);
    }
}

// ============================================================================
// Prep 2: W1/W2 -> fp16 (grid 96x256); block 0 folds BN
// ============================================================================
__global__ __launch_bounds__(256) void prep_w(
    const float* __restrict__ W1, const float* __restrict__ b1,
    const float* __restrict__ g1, const float* __restrict__ be1,
    const float* __restrict__ mu1, const float* __restrict__ va1,
    const float* __restrict__ W2, const float* __restrict__ b2,
    const float* __restrict__ g2, const float* __restrict__ be2,
    const float* __restrict__ mu2, const float* __restrict__ va2)
{
    const int idx = blockIdx.x * 256 + threadIdx.x;
    if (idx < 16384) {
        g_W1[idx] = __float2half_rn(W1[idx]);
    } else {
        int i = idx - 16384;
        g_W2[i] = __float2half_rn(W2[i]);
    }
    if (blockIdx.x == 0) {
        int tid = threadIdx.x;
        if (tid < 128) {
            float s = g1[tid] * rsqrtf(va1[tid] + 1e-5f);
            g_S1[tid] = s;
            g_T1[tid] = (b1[tid] - mu1[tid]) * s + be1[tid];
        }
        if (tid < 64) {
            float s = g2[tid] * rsqrtf(va2[tid] + 1e-5f);
            g_S2[tid] = s;
            g_T2[tid] = (b2[tid] - mu2[tid]) * s + be2[tid];
        }
    }
}

// ============================================================================
// Kernel A: interpolation, fp16 r x fp16 feat, 1 MMA per k-step.
// grid (N/128, B), 256 threads (8 warps x 16 rows), double-buffered cp.async.
// ============================================================================
constexpr int RPB    = 272;                 // smem row pitch bytes (136 halves)
constexpr int BT     = 64 * RPB;            // 17408: one 64x128 fp16 tile
constexpr int OFF_UP = 2 * BT;              // 34816, float4[128]
constexpr int OFF_D0 = OFF_UP + 2048;
constexpr int OFF_D1 = OFF_D0 + 2048;
constexpr int INTERP_SMEM = OFF_D1 + 2048;  // 40960

__global__ __launch_bounds__(256, 2) void interp_kernel(
    const float* __restrict__ xyz_down,
    const float* __restrict__ xyz_up)
{
    extern __shared__ __align__(16) char smem[];
    const u32 sbase = smem_u32(smem);

    const int tid = threadIdx.x, wid = tid >> 5, lane = tid & 31;
    const int b = blockIdx.y, n0 = blockIdx.x * 128;
    const int g = lane >> 2, tg = lane & 3;
    const int r0 = wid * 16;

    auto stageB = [&](int t, int sel) {
        const u32 dstb = sbase + (u32)(sel * BT);
#pragma unroll
        for (int j = 0; j < 4; ++j) {
            int idx = tid + 256 * j;
            int d = idx >> 4, kc = (idx & 15) * 8;
            size_t go = (size_t)(b * 64 + d) * M_ + t * 128 + kc;
            cp16(dstb + (u32)(d * RPB + kc * 2), g_fTh + go);
        }
        CP_COMMIT();
    };
    auto loadD = [&](int t) -> float4 {
        const float* p = xyz_down + ((size_t)b * M_ + t * 128 + tid) * 3;
        float x = p[0] * CSC, y = p[1] * CSC, z = p[2] * CSC;
        return make_float4(x, y, z, x * x + y * y + z * z + EPS2);
    };

    // ---- prologue ----
    stageB(0, 0);
    if (tid < 128) {
        const float* p = xyz_up + ((size_t)b * N_ + n0 + tid) * 3;
        float x = p[0] * CSC, y = p[1] * CSC, z = p[2] * CSC;
        *(float4*)(smem + OFF_UP + tid * 16) = make_float4(x, y, z, x * x + y * y + z * z);
    }
    float4 qnxt = make_float4(0.f, 0.f, 0.f, 0.f);
    if (tid < 128) {
        *(float4*)(smem + OFF_D0 + tid * 16) = loadD(0);
        qnxt = loadD(1);
    }
    CP_WAIT0();
    __syncthreads();

    const float4 uA = *(const float4*)(smem + OFF_UP + (r0 + g) * 16);
    const float4 uB = *(const float4*)(smem + OFF_UP + (r0 + 8 + g) * 16);

    float c[8][4];
#pragma unroll
    for (int i = 0; i < 8; ++i)
#pragma unroll
        for (int j = 0; j < 4; ++j) c[i][j] = 0.f;
    float rsA = 0.f, rsB = 0.f;

    // ldmatrix.x4: lanes 0-15 -> k-step ks frags, 16-31 -> k-step ks+1 (+32B)
    const u32 lbase = (u32)((lane & 7) * RPB + ((lane >> 3) & 1) * 16
                            + ((lane >> 4) & 1) * 32);

    for (int t = 0; t < 16; ++t) {
        const int sel = t & 1;
        if (t < 15) {
            stageB(t + 1, sel ^ 1);
            if (tid < 128)
                *(float4*)(smem + OFF_D0 + (sel ^ 1) * 2048 + tid * 16) = qnxt;
        }
        if (t < 14 && tid < 128) qnxt = loadD(t + 2);

        const float4* sD = (const float4*)(smem + OFF_D0 + sel * 2048);
        const u32 bsel = sbase + (u32)(sel * BT);

#pragma unroll
        for (int ksp = 0; ksp < 4; ++ksp) {        // two k-steps per iter
            const int kb = ksp * 32 + tg * 2;
            u32 ah0[4], ah1[4];
            // ---- k-step 2*ksp ----
            {
                float4 q0 = sD[kb], q1 = sD[kb + 1], q2 = sD[kb + 8], q3 = sD[kb + 9];
                float d00 = fmaf(fmaf(uA.z, q0.z, fmaf(uA.y, q0.y, uA.x * q0.x)), -2.f, uA.w + q0.w);
                float d01 = fmaf(fmaf(uA.z, q1.z, fmaf(uA.y, q1.y, uA.x * q1.x)), -2.f, uA.w + q1.w);
                float d02 = fmaf(fmaf(uA.z, q2.z, fmaf(uA.y, q2.y, uA.x * q2.x)), -2.f, uA.w + q2.w);
                float d03 = fmaf(fmaf(uA.z, q3.z, fmaf(uA.y, q3.y, uA.x * q3.x)), -2.f, uA.w + q3.w);
                float d10 = fmaf(fmaf(uB.z, q0.z, fmaf(uB.y, q0.y, uB.x * q0.x)), -2.f, uB.w + q0.w);
                float d11 = fmaf(fmaf(uB.z, q1.z, fmaf(uB.y, q1.y, uB.x * q1.x)), -2.f, uB.w + q1.w);
                float d12 = fmaf(fmaf(uB.z, q2.z, fmaf(uB.y, q2.y, uB.x * q2.x)), -2.f, uB.w + q2.w);
                float d13 = fmaf(fmaf(uB.z, q3.z, fmaf(uB.y, q3.y, uB.x * q3.x)), -2.f, uB.w + q3.w);
                float r00 = fminf(__fdividef(1.f, d00), 60000.f);
                float r01 = fminf(__fdividef(1.f, d01), 60000.f);
                float r02 = fminf(__fdividef(1.f, d02), 60000.f);
                float r03 = fminf(__fdividef(1.f, d03), 60000.f);
                float r10 = fminf(__fdividef(1.f, d10), 60000.f);
                float r11 = fminf(__fdividef(1.f, d11), 60000.f);
                float r12 = fminf(__fdividef(1.f, d12), 60000.f);
                float r13 = fminf(__fdividef(1.f, d13), 60000.f);
                rsA += (r00 + r01) + (r02 + r03);
                rsB += (r10 + r11) + (r12 + r13);
                ah0[0] = cvt_h2(r01, r00);
                ah0[1] = cvt_h2(r11, r10);
                ah0[2] = cvt_h2(r03, r02);
                ah0[3] = cvt_h2(r13, r12);
            }
            // ---- k-step 2*ksp+1 ----
            {
                float4 q0 = sD[kb + 16], q1 = sD[kb + 17], q2 = sD[kb + 24], q3 = sD[kb + 25];
                float d00 = fmaf(fmaf(uA.z, q0.z, fmaf(uA.y, q0.y, uA.x * q0.x)), -2.f, uA.w + q0.w);
                float d01 = fmaf(fmaf(uA.z, q1.z, fmaf(uA.y, q1.y, uA.x * q1.x)), -2.f, uA.w + q1.w);
                float d02 = fmaf(fmaf(uA.z, q2.z, fmaf(uA.y, q2.y, uA.x * q2.x)), -2.f, uA.w + q2.w);
                float d03 = fmaf(fmaf(uA.z, q3.z, fmaf(uA.y, q3.y, uA.x * q3.x)), -2.f, uA.w + q3.w);
                float d10 = fmaf(fmaf(uB.z, q0.z, fmaf(uB.y, q0.y, uB.x * q0.x)), -2.f, uB.w + q0.w);
                float d11 = fmaf(fmaf(uB.z, q1.z, fmaf(uB.y, q1.y, uB.x * q1.x)), -2.f, uB.w + q1.w);
                float d12 = fmaf(fmaf(uB.z, q2.z, fmaf(uB.y, q2.y, uB.x * q2.x)), -2.f, uB.w + q2.w);
                float d13 = fmaf(fmaf(uB.z, q3.z, fmaf(uB.y, q3.y, uB.x * q3.w ? q3.z : q3.z)), -2.f, uB.w + q3.w);
                // (the ternary above is identity; kept simple below)
                d13 = fmaf(fmaf(uB.z, q3.z, fmaf(uB.y, q3.y, uB.x * q3.x)), -2.f, uB.w + q3.w);
                float r00 = fminf(__fdividef(1.f, d00), 60000.f);
                float r01 = fminf(__fdividef(1.f, d01), 60000.f);
                float r02 = fminf(__fdividef(1.f, d02), 60000.f);
                float r03 = fminf(__fdividef(1.f, d03), 60000.f);
                float r10 = fminf(__fdividef(1.f, d10), 60000.f);
                float r11 = fminf(__fdividef(1.f, d11), 60000.f);
                float r12 = fminf(__fdividef(1.f, d12), 60000.f);
                float r13 = fminf(__fdividef(1.f, d13), 60000.f);
                rsA += (r00 + r01) + (r02 + r03);
                rsB += (r10 + r11) + (r12 + r13);
                ah1[0] = cvt_h2(r01, r00);
                ah1[1] = cvt_h2(r11, r10);
                ah1[2] = cvt_h2(r03, r02);
                ah1[3] = cvt_h2(r13, r12);
            }

            const u32 baddr = bsel + (u32)(ksp * 64) + lbase;
            u32 bf[8][4];
#pragma unroll
            for (int nt = 0; nt < 8; ++nt) ldsm_x4(bf[nt], baddr + (u32)(nt * 8 * RPB));
#pragma unroll
            for (int nt = 0; nt < 8; ++nt) mma_f16(c[nt], ah0, bf[nt][0], bf[nt][1]);
#pragma unroll
            for (int nt = 0; nt < 8; ++nt) mma_f16(c[nt], ah1, bf[nt][2], bf[nt][3]);
        }
        if (t < 15) { CP_WAIT0(); __syncthreads(); }
    }

    // rsum quad-reduce
    rsA += __shfl_xor_sync(0xFFFFFFFFu, rsA, 1);
    rsA += __shfl_xor_sync(0xFFFFFFFFu, rsA, 2);
    rsB += __shfl_xor_sync(0xFFFFFFFFu, rsB, 1);
    rsB += __shfl_xor_sync(0xFFFFFFFFu, rsB, 2);
    const float invA = __fdividef(1.f, rsA);
    const float invB = __fdividef(1.f, rsB);

    float* rowA = g_ibuf + ((size_t)(b * N_ + n0 + r0 + g)) * 64;
    float* rowB = g_ibuf + ((size_t)(b * N_ + n0 + r0 + 8 + g)) * 64;
#pragma unroll
    for (int nt = 0; nt < 8; ++nt) {
        *(float2*)(rowA + nt * 8 + 2 * tg) = make_float2(c[nt][0] * invA, c[nt][1] * invA);
        *(float2*)(rowB + nt * 8 + 2 * tg) = make_float2(c[nt][2] * invB, c[nt][3] * invB);
    }
}

// ============================================================================
// Kernel B: persistent fp16 MLP. grid 256, 2 row-tiles per CTA.
// ============================================================================
constexpr int SMW1B = 128 * RPB;     // 34816 B
constexpr int SMW2B = 64 * RPB;      // 17408 B
constexpr int MLP_SMEM = SMW1B + SMW2B + (128 + 128 + 64 + 64) * 4;
constexpr int NTILES = (B_ * N_) / 128;    // 512

__global__ __launch_bounds__(256) void mlp_kernel(
    const float* __restrict__ feat_up, float* __restrict__ out)
{
    extern __shared__ __align__(16) char sm[];
    __half* sW1 = (__half*)sm;
    __half* sW2 = (__half*)(sm + SMW1B);
    float* sS1 = (float*)(sm + SMW1B + SMW2B);
    float* sT1 = sS1 + 128;
    float* sS2 = sT1 + 128;
    float* sT2 = sS2 + 64;

    const int tid = threadIdx.x, wid = tid >> 5, lane = tid & 31;
    const int g = lane >> 2, tg = lane & 3;
    const int r0 = wid * 16;

    for (int i = tid; i < 2048; i += 256) {
        int r = i >> 4, q = (i & 15) * 8;
        *(uint4*)(sW1 + r * 136 + q) = ((const uint4*)g_W1)[i];
    }
    for (int i = tid; i < 1024; i += 256) {
        int r = i >> 4, q = (i & 15) * 8;
        *(uint4*)(sW2 + r * 136 + q) = ((const uint4*)g_W2)[i];
    }
    if (tid < 128) { sS1[tid] = g_S1[tid]; sT1[tid] = g_T1[tid]; }
    if (tid < 64)  { sS2[tid] = g_S2[tid]; sT2[tid] = g_T2[tid]; }
    __syncthreads();

    const u32 bW1 = smem_u32(sW1), bW2 = smem_u32(sW2);
    // x4 lane addressing: lanes 0-15 -> n-tile ntp*2, 16-31 -> ntp*2+1 (+8 rows)
    const u32 lrow4 = (u32)((lane & 7) * RPB + ((lane >> 3) & 1) * 16
                            + ((lane >> 4) & 1) * (8 * RPB));

    for (int tile = blockIdx.x; tile < NTILES; tile += gridDim.x) {
        const size_t rowA = (size_t)tile * 128 + r0 + g;
        const size_t rowB = rowA + 8;
        const float* fuA = feat_up + rowA * 64;
        const float* fuB = feat_up + rowB * 64;
        const float* ibA = g_ibuf + rowA * 64;
        const float* ibB = g_ibuf + rowB * 64;

        float c1[16][4];
#pragma unroll
        for (int i = 0; i < 16; ++i)
#pragma unroll
            for (int j = 0; j < 4; ++j) c1[i][j] = 0.f;

#pragma unroll
        for (int ks = 0; ks < 8; ++ks) {
            const float* sA = (ks < 4) ? (fuA + ks * 16) : (ibA + (ks - 4) * 16);
            const float* sB = (ks < 4) ? (fuB + ks * 16) : (ibB + (ks - 4) * 16);
            float2 p0 = *(const float2*)(sA + 2 * tg);
            float2 p1 = *(const float2*)(sA + 2 * tg + 8);
            float2 p2 = *(const float2*)(sB + 2 * tg);
            float2 p3 = *(const float2*)(sB + 2 * tg + 8);
            u32 ah[4];
            ah[0] = cvt_h2(p0.y, p0.x);
            ah[1] = cvt_h2(p2.y, p2.x);
            ah[2] = cvt_h2(p1.y, p1.x);
            ah[3] = cvt_h2(p3.y, p3.x);

            const u32 koff = (u32)(ks * 32);
#pragma unroll
            for (int ntp = 0; ntp < 8; ++ntp) {
                u32 bf[4];
                ldsm_x4(bf, bW1 + (u32)(ntp * 16 * RPB) + lrow4 + koff);
                mma_f16(c1[2 * ntp],     ah, bf[0], bf[1]);
                mma_f16(c1[2 * ntp + 1], ah, bf[2], bf[3]);
            }
        }

        // BN1 + relu -> A2 fragments (single fp16)
        u32 a2[8][4];
#pragma unroll
        for (int k2 = 0; k2 < 8; ++k2) {
            int nt0 = 2 * k2, nt1 = 2 * k2 + 1;
            int o0 = nt0 * 8 + 2 * tg, o1 = o0 + 1;
            int o2 = nt1 * 8 + 2 * tg, o3 = o2 + 1;
            float hA0 = fmaxf(fmaf(c1[nt0][0], sS1[o0], sT1[o0]), 0.f);
            float hA1 = fmaxf(fmaf(c1[nt0][1], sS1[o1], sT1[o1]), 0.f);
            float hB0 = fmaxf(fmaf(c1[nt0][2], sS1[o0], sT1[o0]), 0.f);
            float hB1 = fmaxf(fmaf(c1[nt0][3], sS1[o1], sT1[o1]), 0.f);
            float hA2 = fmaxf(fmaf(c1[nt1][0], sS1[o2], sT1[o2]), 0.f);
            float hA3 = fmaxf(fmaf(c1[nt1][1], sS1[o3], sT1[o3]), 0.f);
            float hB2 = fmaxf(fmaf(c1[nt1][2], sS1[o2], sT1[o2]), 0.f);
            float hB3 = fmaxf(fmaf(c1[nt1][3], sS1[o3], sT1[o3]), 0.f);
            a2[k2][0] = cvt_h2(hA1, hA0);
            a2[k2][1] = cvt_h2(hB1, hB0);
            a2[k2][2] = cvt_h2(hA3, hA2);
            a2[k2][3] = cvt_h2(hB3, hB2);
        }

        float c2[8][4];
#pragma unroll
        for (int i = 0; i < 8; ++i)
#pragma unroll
            for (int j = 0; j < 4; ++j) c2[i][j] = 0.f;

#pragma unroll
        for (int k2 = 0; k2 < 8; ++k2) {
            const u32 koff = (u32)(k2 * 32);
#pragma unroll
            for (int ntp = 0; ntp < 4; ++ntp) {
                u32 bf[4];
                ldsm_x4(bf, bW2 + (u32)(ntp * 16 * RPB) + lrow4 + koff);
                mma_f16(c2[2 * ntp],     a2[k2], bf[0], bf[1]);
                mma_f16(c2[2 * ntp + 1], a2[k2], bf[2], bf[3]);
            }
        }

        float* oA = out + rowA * 64;
        float* oB = out + rowB * 64;
#pragma unroll
        for (int nt = 0; nt < 8; ++nt) {
            int j0 = nt * 8 + 2 * tg, j1 = j0 + 1;
            *(float2*)(oA + j0) = make_float2(fmaf(c2[nt][0], sS2[j0], sT2[j0]),
                                              fmaf(c2[nt][1], sS2[j1], sT2[j1]));
            *(float2*)(oB + j0) = make_float2(fmaf(c2[nt][2], sS2[j0], sT2[j0]),
                                              fmaf(c2[nt][3], sS2[j1], sT2[j1]));
        }
    }
}

// ============================================================================
extern "C" void kernel_launch(void* const* d_in, const int* in_sizes, int n_in,
                              void* d_out, int out_size)
{
    const float* xyz_down  = (const float*)d_in[0];
    const float* xyz_up    = (const float*)d_in[1];
    const float* feat_down = (const float*)d_in[2];
    const float* feat_up   = (const float*)d_in[3];
    const float* W1  = (const float*)d_in[4];
    const float* b1  = (const float*)d_in[5];
    const float* g1  = (const float*)d_in[6];
    const float* be1 = (const float*)d_in[7];
    const float* mu1 = (const float*)d_in[8];
    const float* va1 = (const float*)d_in[9];
    const float* W2  = (const float*)d_in[10];
    const float* b2  = (const float*)d_in[11];
    const float* g2  = (const float*)d_in[12];
    const float* be2 = (const float*)d_in[13];
    const float* mu2 = (const float*)d_in[14];
    const float* va2 = (const float*)d_in[15];
    float* out = (float*)d_out;

    prep_feat<<<dim3(M_ / 64, B_), 256>>>(feat_down);
    prep_w<<<96, 256>>>(W1, b1, g1, be1, mu1, va1, W2, b2, g2, be2, mu2, va2);

    cudaFuncSetAttribute(interp_kernel,
                         cudaFuncAttributeMaxDynamicSharedMemorySize, INTERP_SMEM);
    interp_kernel<<<dim3(N_ / 128, B_), 256, INTERP_SMEM>>>(xyz_down, xyz_up);

    cudaFuncSetAttribute(mlp_kernel,
                         cudaFuncAttributeMaxDynamicSharedMemorySize, MLP_SMEM);
    mlp_kernel<<<256, 256, MLP_SMEM>>>(feat_up, out);
}

// round 9
// speedup vs baseline: 7.3648x; 1.1810x over previous
#include <cuda_runtime.h>
#include <cuda_bf16.h>
#include <cuda_fp16.h>

typedef unsigned int u32;

constexpr int B_ = 4;
constexpr int M_ = 2048;
constexpr int N_ = 16384;

// coordinate scale: d' = 256*d, r' = r/256; w = r/Σr invariant
constexpr float CSC  = 16.0f;
constexpr float EPS2 = 2.56e-6f;   // 1e-8 * 256

// ---------------- device scratch ----------------
__device__ float g_ibuf[(size_t)B_ * N_ * 64];     // interp features
__device__ __half g_fTh[(size_t)B_ * 64 * M_];     // featT fp16 (B,64,M)
__device__ __half g_W1[128 * 128];                 // fp16 weights
__device__ __half g_W2[64 * 128];
__device__ float g_S1[128], g_T1[128], g_S2[64], g_T2[64];

// ---------------- helpers ----------------
__device__ __forceinline__ u32 smem_u32(const void* p) {
    u32 a;
    asm("{ .reg .u64 t; cvta.to.shared.u64 t, %1; cvt.u32.u64 %0, t; }" : "=r"(a) : "l"(p));
    return a;
}
__device__ __forceinline__ u32 cvt_h2(float hi, float lo) {
    u32 r;
    asm("cvt.rn.f16x2.f32 %0, %1, %2;" : "=r"(r) : "f"(hi), "f"(lo));
    return r;
}
__device__ __forceinline__ void ldsm_x4(u32* r, u32 addr) {
    asm volatile("ldmatrix.sync.aligned.m8n8.x4.shared.b16 {%0, %1, %2, %3}, [%4];"
                 : "=r"(r[0]), "=r"(r[1]), "=r"(r[2]), "=r"(r[3]) : "r"(addr));
}
__device__ __forceinline__ void mma_f16(float* c, const u32* a, u32 b0, u32 b1) {
    asm volatile(
        "mma.sync.aligned.m16n8k16.row.col.f32.f16.f16.f32 "
        "{%0,%1,%2,%3}, {%4,%5,%6,%7}, {%8,%9}, {%0,%1,%2,%3};"
        : "+f"(c[0]), "+f"(c[1]), "+f"(c[2]), "+f"(c[3])
        : "r"(a[0]), "r"(a[1]), "r"(a[2]), "r"(a[3]), "r"(b0), "r"(b1));
}
__device__ __forceinline__ void cp16(u32 dst, const void* src) {
    asm volatile("cp.async.ca.shared.global [%0], [%1], 16;" :: "r"(dst), "l"(src) : "memory");
}
#define CP_COMMIT() asm volatile("cp.async.commit_group;" ::: "memory")
#define CP_WAIT0()  asm volatile("cp.async.wait_group 0;" ::: "memory")

// hi part (as float) of fp16 rounding
__device__ __forceinline__ float h_hi(float f) {
    return __half2float(__float2half_rn(f));
}

// ============================================================================
// Prep 1: feat_down (B,M,64) f32 -> g_fTh (B,64,M) fp16
// ============================================================================
__global__ __launch_bounds__(256) void prep_feat(const float* __restrict__ feat_down) {
    __shared__ float sT[64][65];
    const int b = blockIdx.y, m0 = blockIdx.x * 64;
    const int tid = threadIdx.x;
#pragma unroll
    for (int j = 0; j < 4; ++j) {
        int i = tid + j * 256;
        int r = i >> 4, c4 = (i & 15) * 4;
        float4 v = *(const float4*)(feat_down + ((size_t)b * M_ + m0 + r) * 64 + c4);
        sT[c4 + 0][r] = v.x; sT[c4 + 1][r] = v.y;
        sT[c4 + 2][r] = v.z; sT[c4 + 3][r] = v.w;
    }
    __syncthreads();
#pragma unroll
    for (int j = 0; j < 8; ++j) {
        int u = tid + j * 256;
        int d = u >> 5, m2 = (u & 31) * 2;
        size_t o = (size_t)(b * 64 + d) * M_ + m0 + m2;
        *(u32*)(g_fTh + o) = cvt_h2(sT[d][m2 + 1], sT[d][m2]);
    }
}

// ============================================================================
// Prep 2: W1/W2 -> fp16 (grid 96x256); block 0 folds BN
// ============================================================================
__global__ __launch_bounds__(256) void prep_w(
    const float* __restrict__ W1, const float* __restrict__ b1,
    const float* __restrict__ g1, const float* __restrict__ be1,
    const float* __restrict__ mu1, const float* __restrict__ va1,
    const float* __restrict__ W2, const float* __restrict__ b2,
    const float* __restrict__ g2, const float* __restrict__ be2,
    const float* __restrict__ mu2, const float* __restrict__ va2)
{
    const int idx = blockIdx.x * 256 + threadIdx.x;
    if (idx < 16384) {
        g_W1[idx] = __float2half_rn(W1[idx]);
    } else {
        int i = idx - 16384;
        g_W2[i] = __float2half_rn(W2[i]);
    }
    if (blockIdx.x == 0) {
        int tid = threadIdx.x;
        if (tid < 128) {
            float s = g1[tid] * rsqrtf(va1[tid] + 1e-5f);
            g_S1[tid] = s;
            g_T1[tid] = (b1[tid] - mu1[tid]) * s + be1[tid];
        }
        if (tid < 64) {
            float s = g2[tid] * rsqrtf(va2[tid] + 1e-5f);
            g_S2[tid] = s;
            g_T2[tid] = (b2[tid] - mu2[tid]) * s + be2[tid];
        }
    }
}

// ============================================================================
// Kernel A: interpolation with TENSORIZED distances.
//   d[16n x 16m] via 2 MMAs over a rank-13 fp16 hi/lo encoding, then
//   r = clamp(rcp(d)) feeds the feature GEMM A-fragments directly.
// grid (N/128, B), 256 threads (8 warps x 16 rows), double-buffered cp.async.
// ============================================================================
constexpr int RPB    = 272;                 // feature smem row pitch bytes
constexpr int BT     = 64 * RPB;            // 17408: one 64x128 fp16 tile
constexpr int XBP    = 48;                  // coord-row pitch bytes (16 halves + pad)
constexpr int XBT    = 128 * XBP;           // 6144: one coord tile
constexpr int OFF_XB0 = 2 * BT;             // 34816
constexpr int OFF_XB1 = OFF_XB0 + XBT;      // 40960
constexpr int OFF_UA  = OFF_XB1 + XBT;      // 47104 (128 x 48 up-point rows)
constexpr int INTERP_SMEM = OFF_UA + XBT;   // 53248

__global__ __launch_bounds__(256, 2) void interp_kernel(
    const float* __restrict__ xyz_down,
    const float* __restrict__ xyz_up)
{
    extern __shared__ __align__(16) char smem[];
    const u32 sbase = smem_u32(smem);

    const int tid = threadIdx.x, wid = tid >> 5, lane = tid & 31;
    const int b = blockIdx.y, n0 = blockIdx.x * 128;
    const int g = lane >> 2, tg = lane & 3;
    const int r0 = wid * 16;

    auto stageB = [&](int t, int sel) {
        const u32 dstb = sbase + (u32)(sel * BT);
#pragma unroll
        for (int j = 0; j < 4; ++j) {
            int idx = tid + 256 * j;
            int d = idx >> 4, kc = (idx & 15) * 8;
            size_t go = (size_t)(b * 64 + d) * M_ + t * 128 + kc;
            cp16(dstb + (u32)(d * RPB + kc * 2), g_fTh + go);
        }
        CP_COMMIT();
    };
    auto loadC = [&](int t) -> float3 {
        const float* p = xyz_down + ((size_t)b * M_ + t * 128 + tid) * 3;
        return make_float3(p[0], p[1], p[2]);
    };
    // build one down-point coord row (B operand of the distance GEMM)
    auto buildXB = [&](int sel, float3 cr) {
        float bx = cr.x * CSC, by = cr.y * CSC, bz = cr.z * CSC;
        float m2 = bx * bx + by * by + bz * bz + EPS2;
        float cx = -2.f * bx, cy = -2.f * by, cz = -2.f * bz;
        float hx = h_hi(cx), hy = h_hi(cy), hz = h_hi(cz), hm = h_hi(m2);
        u32 w0 = cvt_h2(hy, hx);
        u32 w1 = cvt_h2(hx, hz);
        u32 w2 = cvt_h2(hz, hy);
        u32 w3 = cvt_h2(cy - hy, cx - hx);
        u32 w4 = cvt_h2(1.f, cz - hz);
        u32 w5 = cvt_h2(hm, 1.f);
        u32 w6 = cvt_h2(0.f, m2 - hm);
        u32 dst = sbase + (u32)(OFF_XB0 + sel * XBT + tid * XBP);
        asm volatile("st.shared.v4.b32 [%0], {%1,%2,%3,%4};"
                     :: "r"(dst), "r"(w0), "r"(w1), "r"(w2), "r"(w3));
        asm volatile("st.shared.v4.b32 [%0], {%1,%2,%3,%4};"
                     :: "r"(dst + 16), "r"(w4), "r"(w5), "r"(w6), "r"(0u));
    };

    // ---------------- prologue ----------------
    stageB(0, 0);
    if (tid < 128) {
        // up-point row (A operand of the distance GEMM)
        const float* p = xyz_up + ((size_t)b * N_ + n0 + tid) * 3;
        float ax = p[0] * CSC, ay = p[1] * CSC, az = p[2] * CSC;
        float n2 = ax * ax + ay * ay + az * az;
        float hx = h_hi(ax), hy = h_hi(ay), hz = h_hi(az), hn = h_hi(n2);
        u32 w0 = cvt_h2(hy, hx);
        u32 w1 = cvt_h2(ax - hx, hz);
        u32 w2 = cvt_h2(az - hz, ay - hy);
        u32 w3 = cvt_h2(hy, hx);
        u32 w4 = cvt_h2(hn, hz);
        u32 w5 = cvt_h2(1.f, n2 - hn);
        u32 w6 = cvt_h2(0.f, 1.f);
        u32 dst = sbase + (u32)(OFF_UA + tid * XBP);
        asm volatile("st.shared.v4.b32 [%0], {%1,%2,%3,%4};"
                     :: "r"(dst), "r"(w0), "r"(w1), "r"(w2), "r"(w3));
        asm volatile("st.shared.v4.b32 [%0], {%1,%2,%3,%4};"
                     :: "r"(dst + 16), "r"(w4), "r"(w5), "r"(w6), "r"(0u));
    }
    float3 cn = make_float3(0.f, 0.f, 0.f);
    if (tid < 128) {
        buildXB(0, loadC(0));
        cn = loadC(1);
    }
    CP_WAIT0();
    __syncthreads();

    // constant distance-A fragment (rows r0..r0+15, 16 channels)
    u32 aD[4];
    ldsm_x4(aD, sbase + (u32)(OFF_UA + (r0 + (lane & 15)) * XBP + (lane >> 4) * 16));

    float c[8][4];
#pragma unroll
    for (int i = 0; i < 8; ++i)
#pragma unroll
        for (int j = 0; j < 4; ++j) c[i][j] = 0.f;
    float rsA = 0.f, rsB = 0.f;

    // feature ldmatrix.x4 lane base (2 k-steps per fetch)
    const u32 lbaseF = (u32)((lane & 7) * RPB + ((lane >> 3) & 1) * 16
                             + ((lane >> 4) & 1) * 32);
    // distance-B ldmatrix.x4 lane base (16 m-points, both col groups)
    const u32 lbaseX = (u32)(((lane & 7) + ((lane >> 4) & 1) * 8) * XBP
                             + ((lane >> 3) & 1) * 16);

    for (int t = 0; t < 16; ++t) {
        const int sel = t & 1;
        if (t < 15) {
            stageB(t + 1, sel ^ 1);
            if (tid < 128) buildXB(sel ^ 1, cn);
        }
        if (t < 14 && tid < 128) cn = loadC(t + 2);

        const u32 fsel = sbase + (u32)(sel * BT);
        const u32 xsel = sbase + (u32)(OFF_XB0 + sel * XBT) + lbaseX;

#pragma unroll
        for (int ksp = 0; ksp < 4; ++ksp) {
            u32 ah0[4], ah1[4];
#pragma unroll
            for (int sub = 0; sub < 2; ++sub) {
                const int s = ksp * 2 + sub;
                u32 bx[4];
                ldsm_x4(bx, xsel + (u32)(s * 16 * XBP));
                float cd[8];
#pragma unroll
                for (int i = 0; i < 8; ++i) cd[i] = 0.f;
                mma_f16(cd,     aD, bx[0], bx[1]);   // m-cols 16s+0..7
                mma_f16(cd + 4, aD, bx[2], bx[3]);   // m-cols 16s+8..15
                float q0 = fminf(__fdividef(1.f, cd[0]), 60000.f);
                float q1 = fminf(__fdividef(1.f, cd[1]), 60000.f);
                float q2 = fminf(__fdividef(1.f, cd[2]), 60000.f);
                float q3 = fminf(__fdividef(1.f, cd[3]), 60000.f);
                float q4 = fminf(__fdividef(1.f, cd[4]), 60000.f);
                float q5 = fminf(__fdividef(1.f, cd[5]), 60000.f);
                float q6 = fminf(__fdividef(1.f, cd[6]), 60000.f);
                float q7 = fminf(__fdividef(1.f, cd[7]), 60000.f);
                rsA += (q0 + q1) + (q4 + q5);
                rsB += (q2 + q3) + (q6 + q7);
                u32* ah = sub ? ah1 : ah0;
                ah[0] = cvt_h2(q1, q0);
                ah[1] = cvt_h2(q3, q2);
                ah[2] = cvt_h2(q5, q4);
                ah[3] = cvt_h2(q7, q6);
            }
            const u32 baddr = fsel + (u32)(ksp * 64) + lbaseF;
            u32 bf[8][4];
#pragma unroll
            for (int nt = 0; nt < 8; ++nt) ldsm_x4(bf[nt], baddr + (u32)(nt * 8 * RPB));
#pragma unroll
            for (int nt = 0; nt < 8; ++nt) mma_f16(c[nt], ah0, bf[nt][0], bf[nt][1]);
#pragma unroll
            for (int nt = 0; nt < 8; ++nt) mma_f16(c[nt], ah1, bf[nt][2], bf[nt][3]);
        }
        if (t < 15) { CP_WAIT0(); __syncthreads(); }
    }

    // rsum quad-reduce (lanes of a quad cover all 16 m-cols per k-step)
    rsA += __shfl_xor_sync(0xFFFFFFFFu, rsA, 1);
    rsA += __shfl_xor_sync(0xFFFFFFFFu, rsA, 2);
    rsB += __shfl_xor_sync(0xFFFFFFFFu, rsB, 1);
    rsB += __shfl_xor_sync(0xFFFFFFFFu, rsB, 2);
    const float invA = __fdividef(1.f, rsA);
    const float invB = __fdividef(1.f, rsB);

    float* rowA = g_ibuf + ((size_t)(b * N_ + n0 + r0 + g)) * 64;
    float* rowB = g_ibuf + ((size_t)(b * N_ + n0 + r0 + 8 + g)) * 64;
#pragma unroll
    for (int nt = 0; nt < 8; ++nt) {
        *(float2*)(rowA + nt * 8 + 2 * tg) = make_float2(c[nt][0] * invA, c[nt][1] * invA);
        *(float2*)(rowB + nt * 8 + 2 * tg) = make_float2(c[nt][2] * invB, c[nt][3] * invB);
    }
}

// ============================================================================
// Kernel B: persistent fp16 MLP (unchanged from R7). grid 256.
// ============================================================================
constexpr int SMW1B = 128 * RPB;     // 34816 B
constexpr int SMW2B = 64 * RPB;      // 17408 B
constexpr int MLP_SMEM = SMW1B + SMW2B + (128 + 128 + 64 + 64) * 4;
constexpr int NTILES = (B_ * N_) / 128;    // 512

__global__ __launch_bounds__(256) void mlp_kernel(
    const float* __restrict__ feat_up, float* __restrict__ out)
{
    extern __shared__ __align__(16) char sm[];
    __half* sW1 = (__half*)sm;
    __half* sW2 = (__half*)(sm + SMW1B);
    float* sS1 = (float*)(sm + SMW1B + SMW2B);
    float* sT1 = sS1 + 128;
    float* sS2 = sT1 + 128;
    float* sT2 = sS2 + 64;

    const int tid = threadIdx.x, wid = tid >> 5, lane = tid & 31;
    const int g = lane >> 2, tg = lane & 3;
    const int r0 = wid * 16;

    for (int i = tid; i < 2048; i += 256) {
        int r = i >> 4, q = (i & 15) * 8;
        *(uint4*)(sW1 + r * 136 + q) = ((const uint4*)g_W1)[i];
    }
    for (int i = tid; i < 1024; i += 256) {
        int r = i >> 4, q = (i & 15) * 8;
        *(uint4*)(sW2 + r * 136 + q) = ((const uint4*)g_W2)[i];
    }
    if (tid < 128) { sS1[tid] = g_S1[tid]; sT1[tid] = g_T1[tid]; }
    if (tid < 64)  { sS2[tid] = g_S2[tid]; sT2[tid] = g_T2[tid]; }
    __syncthreads();

    const u32 bW1 = smem_u32(sW1), bW2 = smem_u32(sW2);
    const u32 lrow4 = (u32)((lane & 7) * RPB + ((lane >> 3) & 1) * 16
                            + ((lane >> 4) & 1) * (8 * RPB));

    for (int tile = blockIdx.x; tile < NTILES; tile += gridDim.x) {
        const size_t rowA = (size_t)tile * 128 + r0 + g;
        const size_t rowB = rowA + 8;
        const float* fuA = feat_up + rowA * 64;
        const float* fuB = feat_up + rowB * 64;
        const float* ibA = g_ibuf + rowA * 64;
        const float* ibB = g_ibuf + rowB * 64;

        float c1[16][4];
#pragma unroll
        for (int i = 0; i < 16; ++i)
#pragma unroll
            for (int j = 0; j < 4; ++j) c1[i][j] = 0.f;

#pragma unroll
        for (int ks = 0; ks < 8; ++ks) {
            const float* sA = (ks < 4) ? (fuA + ks * 16) : (ibA + (ks - 4) * 16);
            const float* sB = (ks < 4) ? (fuB + ks * 16) : (ibB + (ks - 4) * 16);
            float2 p0 = *(const float2*)(sA + 2 * tg);
            float2 p1 = *(const float2*)(sA + 2 * tg + 8);
            float2 p2 = *(const float2*)(sB + 2 * tg);
            float2 p3 = *(const float2*)(sB + 2 * tg + 8);
            u32 ah[4];
            ah[0] = cvt_h2(p0.y, p0.x);
            ah[1] = cvt_h2(p2.y, p2.x);
            ah[2] = cvt_h2(p1.y, p1.x);
            ah[3] = cvt_h2(p3.y, p3.x);

            const u32 koff = (u32)(ks * 32);
#pragma unroll
            for (int ntp = 0; ntp < 8; ++ntp) {
                u32 bf[4];
                ldsm_x4(bf, bW1 + (u32)(ntp * 16 * RPB) + lrow4 + koff);
                mma_f16(c1[2 * ntp],     ah, bf[0], bf[1]);
                mma_f16(c1[2 * ntp + 1], ah, bf[2], bf[3]);
            }
        }

        u32 a2[8][4];
#pragma unroll
        for (int k2 = 0; k2 < 8; ++k2) {
            int nt0 = 2 * k2, nt1 = 2 * k2 + 1;
            int o0 = nt0 * 8 + 2 * tg, o1 = o0 + 1;
            int o2 = nt1 * 8 + 2 * tg, o3 = o2 + 1;
            float hA0 = fmaxf(fmaf(c1[nt0][0], sS1[o0], sT1[o0]), 0.f);
            float hA1 = fmaxf(fmaf(c1[nt0][1], sS1[o1], sT1[o1]), 0.f);
            float hB0 = fmaxf(fmaf(c1[nt0][2], sS1[o0], sT1[o0]), 0.f);
            float hB1 = fmaxf(fmaf(c1[nt0][3], sS1[o1], sT1[o1]), 0.f);
            float hA2 = fmaxf(fmaf(c1[nt1][0], sS1[o2], sT1[o2]), 0.f);
            float hA3 = fmaxf(fmaf(c1[nt1][1], sS1[o3], sT1[o3]), 0.f);
            float hB2 = fmaxf(fmaf(c1[nt1][2], sS1[o2], sT1[o2]), 0.f);
            float hB3 = fmaxf(fmaf(c1[nt1][3], sS1[o3], sT1[o3]), 0.f);
            a2[k2][0] = cvt_h2(hA1, hA0);
            a2[k2][1] = cvt_h2(hB1, hB0);
            a2[k2][2] = cvt_h2(hA3, hA2);
            a2[k2][3] = cvt_h2(hB3, hB2);
        }

        float c2[8][4];
#pragma unroll
        for (int i = 0; i < 8; ++i)
#pragma unroll
            for (int j = 0; j < 4; ++j) c2[i][j] = 0.f;

#pragma unroll
        for (int k2 = 0; k2 < 8; ++k2) {
            const u32 koff = (u32)(k2 * 32);
#pragma unroll
            for (int ntp = 0; ntp < 4; ++ntp) {
                u32 bf[4];
                ldsm_x4(bf, bW2 + (u32)(ntp * 16 * RPB) + lrow4 + koff);
                mma_f16(c2[2 * ntp],     a2[k2], bf[0], bf[1]);
                mma_f16(c2[2 * ntp + 1], a2[k2], bf[2], bf[3]);
            }
        }

        float* oA = out + rowA * 64;
        float* oB = out + rowB * 64;
#pragma unroll
        for (int nt = 0; nt < 8; ++nt) {
            int j0 = nt * 8 + 2 * tg, j1 = j0 + 1;
            *(float2*)(oA + j0) = make_float2(fmaf(c2[nt][0], sS2[j0], sT2[j0]),
                                              fmaf(c2[nt][1], sS2[j1], sT2[j1]));
            *(float2*)(oB + j0) = make_float2(fmaf(c2[nt][2], sS2[j0], sT2[j0]),
                                              fmaf(c2[nt][3], sS2[j1], sT2[j1]));
        }
    }
}

// ============================================================================
extern "C" void kernel_launch(void* const* d_in, const int* in_sizes, int n_in,
                              void* d_out, int out_size)
{
    const float* xyz_down  = (const float*)d_in[0];
    const float* xyz_up    = (const float*)d_in[1];
    const float* feat_down = (const float*)d_in[2];
    const float* feat_up   = (const float*)d_in[3];
    const float* W1  = (const float*)d_in[4];
    const float* b1  = (const float*)d_in[5];
    const float* g1  = (const float*)d_in[6];
    const float* be1 = (const float*)d_in[7];
    const float* mu1 = (const float*)d_in[8];
    const float* va1 = (const float*)d_in[9];
    const float* W2  = (const float*)d_in[10];
    const float* b2  = (const float*)d_in[11];
    const float* g2  = (const float*)d_in[12];
    const float* be2 = (const float*)d_in[13];
    const float* mu2 = (const float*)d_in[14];
    const float* va2 = (const float*)d_in[15];
    float* out = (float*)d_out;

    prep_feat<<<dim3(M_ / 64, B_), 256>>>(feat_down);
    prep_w<<<96, 256>>>(W1, b1, g1, be1, mu1, va1, W2, b2, g2, be2, mu2, va2);

    cudaFuncSetAttribute(interp_kernel,
                         cudaFuncAttributeMaxDynamicSharedMemorySize, INTERP_SMEM);
    interp_kernel<<<dim3(N_ / 128, B_), 256, INTERP_SMEM>>>(xyz_down, xyz_up);

    cudaFuncSetAttribute(mlp_kernel,
                         cudaFuncAttributeMaxDynamicSharedMemorySize, MLP_SMEM);
    mlp_kernel<<<256, 256, MLP_SMEM>>>(feat_up, out);
}